// round 7
// baseline (speedup 1.0000x reference)
#include <cuda_runtime.h>
#include <cuda_bf16.h>
#include <math.h>

#define D_MODEL 1024
#define NH 16
#define HD 64
#define BATCH 2
#define SEQ 2048
#define MROWS (BATCH*SEQ)

// Scratch: q,k,v in [B,H,S,HD], ctx in [B*S, D_MODEL]
__device__ float g_q[BATCH*NH*SEQ*HD];
__device__ float g_k[BATCH*NH*SEQ*HD];
__device__ float g_v[BATCH*NH*SEQ*HD];
__device__ float g_ctx[MROWS*D_MODEL];

__device__ __forceinline__ unsigned f2tf(float x) {
    unsigned r;
    asm("cvt.rna.tf32.f32 %0, %1;" : "=r"(r) : "f"(x));
    return r;
}

__device__ __forceinline__ void mma8(float* c, uint4 a, uint2 b) {
    asm volatile(
        "mma.sync.aligned.m16n8k8.row.col.f32.tf32.tf32.f32 "
        "{%0,%1,%2,%3}, {%4,%5,%6,%7}, {%8,%9}, {%0,%1,%2,%3};"
        : "+f"(c[0]), "+f"(c[1]), "+f"(c[2]), "+f"(c[3])
        : "r"(a.x), "r"(a.y), "r"(a.z), "r"(a.w), "r"(b.x), "r"(b.y));
}

// Fragment-native smem layouts (tf32 words):
// A-layout (16-row m-blocks x 8-col k-blocks): block = (kb*NMB + mb), 512B each;
//   within: lane = (r%8)*4 + (k%4) -> lane*16; reg = (r%16)/8 + 2*((k%8)/4) -> +reg*4.
//   Read: one LDS.128 per (mb,kb) per warp -> a-frag {a0,a1,a2,a3} in order.
// B-layout (8-col n-blocks x 8-row k-blocks): block = (kb*NNB + nb), 256B each;
//   within: lane = (n%8)*4 + (k%4) -> lane*8; reg = (k%8)/4 -> +reg*4.
//   Read: one LDS.64 per (nb,kb) per warp -> b-frag {b0,b1}.

// ============================================================================
// TF32 GEMM, fused over z: Y = X @ W^T. 8 warps (2x4), warp tile 64x32.
// Tile 128x128, K chunks of 32. Register-prefetch double buffer.
// ============================================================================
#define TBM 128
#define TBN 128
#define TBK 32
#define A_BYTES (TBM*TBK*4)      // 16384, frag A-layout (NMB=8, NKB=4)
#define B_BYTES (TBN*TBK*4)      // 16384, frag B-layout (NNB=16)
#define STG (A_BYTES + B_BYTES)
#define GSMEM (2*STG)            // 65536

__global__ __launch_bounds__(256, 2) void gemm_tf32(
    const float* __restrict__ X,
    const float* __restrict__ W0, const float* __restrict__ W1, const float* __restrict__ W2,
    float* __restrict__ Y0, float* __restrict__ Y1, float* __restrict__ Y2,
    int proj_mode)
{
    extern __shared__ char gsm[];
    const int tid = threadIdx.x;
    const int wid = tid >> 5, lane = tid & 31;
    const int g = lane >> 2, tq = lane & 3;
    const int wm = wid & 1, wn = wid >> 1;      // 2 x 4 warp grid
    const int bm = blockIdx.y * TBM, bn = blockIdx.x * TBN;
    const int z = blockIdx.z;
    const float* W = (z == 0) ? W0 : (z == 1) ? W1 : W2;
    float* Y = (z == 0) ? Y0 : (z == 1) ? Y1 : Y2;

    float acc[4][4][4];
    #pragma unroll
    for (int i = 0; i < 4; i++)
        #pragma unroll
        for (int j = 0; j < 4; j++)
            #pragma unroll
            for (int r = 0; r < 4; r++) acc[i][j][r] = 0.f;

    float4 pa[4], pb[4];
    auto ldregs = [&](int kt) {
        #pragma unroll
        for (int i = 0; i < 4; i++) {
            int c = tid + i * 256, r = c >> 3, k4 = (c & 7) << 2;
            pa[i] = *(const float4*)(X + (size_t)(bm + r) * D_MODEL + kt + k4);
            pb[i] = *(const float4*)(W + (size_t)(bn + r) * D_MODEL + kt + k4);
        }
    };
    auto stg = [&](int buf) {
        char* Ab = gsm + buf * STG;
        char* Bb = Ab + A_BYTES;
        #pragma unroll
        for (int i = 0; i < 4; i++) {
            int c = tid + i * 256, r = c >> 3, k4 = (c & 7) << 2;
            // A: base = (kb*8 + mb)*512 + (r%8)*64 + rowbit*4 + colhalf*8 ; +j*16
            unsigned ab = (unsigned)(((k4 >> 3) * 8 + (r >> 4)) * 512
                        + (r & 7) * 64 + ((r >> 3) & 1) * 4 + ((k4 >> 2) & 1) * 8);
            *(unsigned*)(Ab + ab +  0) = f2tf(pa[i].x);
            *(unsigned*)(Ab + ab + 16) = f2tf(pa[i].y);
            *(unsigned*)(Ab + ab + 32) = f2tf(pa[i].z);
            *(unsigned*)(Ab + ab + 48) = f2tf(pa[i].w);
            // B: base = (kb*16 + nb)*256 + (r%8)*32 + colhalf*4 ; +j*8
            unsigned bb = (unsigned)(((k4 >> 3) * 16 + (r >> 3)) * 256
                        + (r & 7) * 32 + ((k4 >> 2) & 1) * 4);
            *(unsigned*)(Bb + bb +  0) = f2tf(pb[i].x);
            *(unsigned*)(Bb + bb +  8) = f2tf(pb[i].y);
            *(unsigned*)(Bb + bb + 16) = f2tf(pb[i].z);
            *(unsigned*)(Bb + bb + 24) = f2tf(pb[i].w);
        }
    };

    ldregs(0);
    const int NCH = D_MODEL / TBK;   // 32
    for (int j = 0; j < NCH; j++) {
        const int buf = j & 1;
        stg(buf);
        __syncthreads();
        if (j + 1 < NCH) ldregs((j + 1) * TBK);

        const char* Ab = gsm + buf * STG;
        const char* Bb = Ab + A_BYTES;
        #pragma unroll
        for (int kk8 = 0; kk8 < 4; kk8++) {
            uint4 a[4];
            #pragma unroll
            for (int mt = 0; mt < 4; mt++)
                a[mt] = *(const uint4*)(Ab + ((kk8 * 8 + wm * 4 + mt) << 9) + lane * 16);
            uint2 b[4];
            #pragma unroll
            for (int nt = 0; nt < 4; nt++)
                b[nt] = *(const uint2*)(Bb + ((kk8 * 16 + wn * 4 + nt) << 8) + lane * 8);
            #pragma unroll
            for (int mt = 0; mt < 4; mt++)
                #pragma unroll
                for (int nt = 0; nt < 4; nt++)
                    mma8(acc[mt][nt], a[mt], b[nt]);
        }
        __syncthreads();
    }

    // epilogue
    #pragma unroll
    for (int mt = 0; mt < 4; mt++) {
        #pragma unroll
        for (int nt = 0; nt < 4; nt++) {
            int row0 = bm + wm * 64 + mt * 16 + g;
            int col = bn + wn * 32 + nt * 8 + tq * 2;
            #pragma unroll
            for (int half = 0; half < 2; half++) {
                int row = row0 + half * 8;
                float v0 = acc[mt][nt][half * 2 + 0];
                float v1 = acc[mt][nt][half * 2 + 1];
                if (proj_mode) {
                    int b2 = row >> 11, s2 = row & (SEQ - 1);
                    int hh = col >> 6, d0 = col & 63;
                    float* dst = Y + ((size_t)((b2 * NH + hh) * SEQ + s2)) * HD + d0;
                    dst[0] = v0; dst[1] = v1;
                } else {
                    float* dst = Y + (size_t)row * D_MODEL + col;
                    dst[0] = v0; dst[1] = v1;
                }
            }
        }
    }
}

// ============================================================================
// Causal flash attention: TF32 mma.sync, 128-row Q tiles, 8 warps, 64-row KV
// tiles. Q/P in frag A-layout, K/V in frag B-layout -> LDS.128/LDS.64 frags.
// ============================================================================
#define QT 128
#define KT 64
#define SQ_OFF 0                        // Q: 128x64 A-layout, 32KB
#define SK_OFF 32768                    // K: 64x64 B-layout, 16KB
#define SV_OFF 49152                    // V: 64x64 B-layout (n=d,k=kv), 16KB
#define SP_OFF 65536                    // P: 128x64 A-layout, 32KB
#define FSMEM 98304

__global__ __launch_bounds__(256, 2) void flash_kernel()
{
    extern __shared__ char smf[];
    char* Qb = smf + SQ_OFF;
    char* Kb = smf + SK_OFF;
    char* Vb = smf + SV_OFF;
    char* Pb = smf + SP_OFF;

    const int tid = threadIdx.x;
    const int w = tid >> 5, lane = tid & 31;
    const int g = lane >> 2, tq = lane & 3;
    const int bh = blockIdx.y;
    const int b = bh / NH, h = bh % NH;
    const int qt = (gridDim.x - 1 - blockIdx.x);   // heavy blocks first
    const int q0 = qt * QT;

    const float* qbase = g_q + (size_t)(b * NH + h) * SEQ * HD;
    const float* kbase = g_k + (size_t)(b * NH + h) * SEQ * HD;
    const float* vbase = g_v + (size_t)(b * NH + h) * SEQ * HD;

    // load Q tile (128x64) into A-layout, pre-scaled by 1/sqrt(HD)
    #pragma unroll
    for (int i = 0; i < 8; i++) {
        int c = tid + i * 256, r = c >> 4, c4 = (c & 15) << 2;
        float4 vq = *(const float4*)(qbase + (size_t)(q0 + r) * HD + c4);
        unsigned qb = (unsigned)(((c4 >> 3) * 8 + (r >> 4)) * 512
                    + (r & 7) * 64 + ((r >> 3) & 1) * 4 + ((c4 >> 2) & 1) * 8);
        *(unsigned*)(Qb + qb +  0) = f2tf(vq.x * 0.125f);
        *(unsigned*)(Qb + qb + 16) = f2tf(vq.y * 0.125f);
        *(unsigned*)(Qb + qb + 32) = f2tf(vq.z * 0.125f);
        *(unsigned*)(Qb + qb + 48) = f2tf(vq.w * 0.125f);
    }

    float o[8][4];
    #pragma unroll
    for (int nt = 0; nt < 8; nt++)
        #pragma unroll
        for (int r = 0; r < 4; r++) o[nt][r] = 0.f;
    float m0 = -INFINITY, m1 = -INFINITY, l0 = 0.f, l1 = 0.f;

    const int prow = w * 16 + g;
    const int row0g = q0 + prow;
    const int row1g = row0g + 8;

    // P store bases (A-layout): col = nt*8 + 2tq + {0,1}
    const unsigned pt0 = (unsigned)(w * 512 + g * 64
                       + ((2 * tq) & 3) * 16 + (((2 * tq) >> 2) & 1) * 8);
    const unsigned pt1 = (unsigned)(w * 512 + g * 64
                       + ((2 * tq + 1) & 3) * 16 + (((2 * tq + 1) >> 2) & 1) * 8);

    const int ktiles = 2 * qt + 2;
    for (int kt = 0; kt < ktiles; kt++) {
        const int kv0 = kt * KT;
        // load K, V tiles (64x64 each) into frag B-layouts
        #pragma unroll
        for (int i = 0; i < 4; i++) {
            int c = tid + i * 256, r = c >> 4, c4 = (c & 15) << 2;
            float4 vk = *(const float4*)(kbase + (size_t)(kv0 + r) * HD + c4);
            // K element (n=r, k=c4+j): base + j*8
            unsigned kb = (unsigned)(((c4 >> 3) * 8 + (r >> 3)) * 256
                        + (r & 7) * 32 + ((c4 >> 2) & 1) * 4);
            *(unsigned*)(Kb + kb +  0) = f2tf(vk.x);
            *(unsigned*)(Kb + kb +  8) = f2tf(vk.y);
            *(unsigned*)(Kb + kb + 16) = f2tf(vk.z);
            *(unsigned*)(Kb + kb + 24) = f2tf(vk.w);
            float4 vv = *(const float4*)(vbase + (size_t)(kv0 + r) * HD + c4);
            // V element (n=c4+j, k=r): lane=(c%8)*4+(r%4), reg=(r%8)/4 -> +j*32
            unsigned vb = (unsigned)(((r >> 3) * 8 + (c4 >> 3)) * 256
                        + ((c4 & 7) * 4 + (r & 3)) * 8 + ((r >> 2) & 1) * 4);
            *(unsigned*)(Vb + vb +  0) = f2tf(vv.x);
            *(unsigned*)(Vb + vb + 32) = f2tf(vv.y);
            *(unsigned*)(Vb + vb + 64) = f2tf(vv.z);
            *(unsigned*)(Vb + vb + 96) = f2tf(vv.w);
        }
        __syncthreads();

        // scores S = Q K^T (16 rows x 64 cols per warp)
        float sc[8][4];
        #pragma unroll
        for (int nt = 0; nt < 8; nt++)
            #pragma unroll
            for (int r = 0; r < 4; r++) sc[nt][r] = 0.f;
        #pragma unroll
        for (int kk8 = 0; kk8 < 8; kk8++) {
            uint4 a = *(const uint4*)(Qb + ((kk8 * 8 + w) << 9) + lane * 16);
            #pragma unroll
            for (int nt = 0; nt < 8; nt++) {
                uint2 bb = *(const uint2*)(Kb + ((kk8 * 8 + nt) << 8) + lane * 8);
                mma8(sc[nt], a, bb);
            }
        }

        // causal mask
        const bool msk0 = (kv0 + KT - 1 > row0g);
        const bool msk1 = (kv0 + KT - 1 > row1g);
        if (msk0 | msk1) {
            #pragma unroll
            for (int nt = 0; nt < 8; nt++) {
                int c0 = kv0 + nt * 8 + tq * 2;
                if (msk0) {
                    if (c0     > row0g) sc[nt][0] = -1e30f;
                    if (c0 + 1 > row0g) sc[nt][1] = -1e30f;
                }
                if (msk1) {
                    if (c0     > row1g) sc[nt][2] = -1e30f;
                    if (c0 + 1 > row1g) sc[nt][3] = -1e30f;
                }
            }
        }

        // online softmax
        float rm0 = -1e30f, rm1 = -1e30f;
        #pragma unroll
        for (int nt = 0; nt < 8; nt++) {
            rm0 = fmaxf(rm0, fmaxf(sc[nt][0], sc[nt][1]));
            rm1 = fmaxf(rm1, fmaxf(sc[nt][2], sc[nt][3]));
        }
        rm0 = fmaxf(rm0, __shfl_xor_sync(0xffffffffu, rm0, 1));
        rm0 = fmaxf(rm0, __shfl_xor_sync(0xffffffffu, rm0, 2));
        rm1 = fmaxf(rm1, __shfl_xor_sync(0xffffffffu, rm1, 1));
        rm1 = fmaxf(rm1, __shfl_xor_sync(0xffffffffu, rm1, 2));

        float nm0 = fmaxf(m0, rm0), nm1 = fmaxf(m1, rm1);
        float a0 = __expf(m0 - nm0), a1 = __expf(m1 - nm1);
        m0 = nm0; m1 = nm1;

        float rs0 = 0.f, rs1 = 0.f;
        #pragma unroll
        for (int nt = 0; nt < 8; nt++) {
            float p0 = __expf(sc[nt][0] - nm0); sc[nt][0] = p0; rs0 += p0;
            float p1 = __expf(sc[nt][1] - nm0); sc[nt][1] = p1; rs0 += p1;
            float p2 = __expf(sc[nt][2] - nm1); sc[nt][2] = p2; rs1 += p2;
            float p3 = __expf(sc[nt][3] - nm1); sc[nt][3] = p3; rs1 += p3;
        }
        rs0 += __shfl_xor_sync(0xffffffffu, rs0, 1);
        rs0 += __shfl_xor_sync(0xffffffffu, rs0, 2);
        rs1 += __shfl_xor_sync(0xffffffffu, rs1, 1);
        rs1 += __shfl_xor_sync(0xffffffffu, rs1, 2);
        l0 = l0 * a0 + rs0;
        l1 = l1 * a1 + rs1;

        #pragma unroll
        for (int nt = 0; nt < 8; nt++) {
            o[nt][0] *= a0; o[nt][1] *= a0;
            o[nt][2] *= a1; o[nt][3] *= a1;
        }

        // write P into A-layout (warp-private rows; rowbit(+8) -> +4 bytes)
        #pragma unroll
        for (int nt = 0; nt < 8; nt++) {
            unsigned a0o = (unsigned)(nt * 4096) + pt0;
            unsigned a1o = (unsigned)(nt * 4096) + pt1;
            *(unsigned*)(Pb + a0o)     = f2tf(sc[nt][0]);
            *(unsigned*)(Pb + a1o)     = f2tf(sc[nt][1]);
            *(unsigned*)(Pb + a0o + 4) = f2tf(sc[nt][2]);
            *(unsigned*)(Pb + a1o + 4) = f2tf(sc[nt][3]);
        }
        __syncwarp();

        // O += P V
        #pragma unroll
        for (int kk8 = 0; kk8 < 8; kk8++) {
            uint4 a = *(const uint4*)(Pb + ((kk8 * 8 + w) << 9) + lane * 16);
            #pragma unroll
            for (int nt = 0; nt < 8; nt++) {
                uint2 bb = *(const uint2*)(Vb + ((kk8 * 8 + nt) << 8) + lane * 8);
                mma8(o[nt], a, bb);
            }
        }
        __syncthreads();   // protect Kb/Vb before next iteration's stores
    }

    // epilogue: normalize, write ctx[b*S + row][h*64 + d]
    float inv0 = 1.f / l0, inv1 = 1.f / l1;
    #pragma unroll
    for (int nt = 0; nt < 8; nt++) {
        int colg = h * HD + nt * 8 + tq * 2;
        size_t r0 = (size_t)(b * SEQ + row0g) * D_MODEL + colg;
        size_t r1 = (size_t)(b * SEQ + row1g) * D_MODEL + colg;
        g_ctx[r0]     = o[nt][0] * inv0;
        g_ctx[r0 + 1] = o[nt][1] * inv0;
        g_ctx[r1]     = o[nt][2] * inv1;
        g_ctx[r1 + 1] = o[nt][3] * inv1;
    }
}

// ============================================================================
extern "C" void kernel_launch(void* const* d_in, const int* in_sizes, int n_in,
                              void* d_out, int out_size)
{
    const float* x  = (const float*)d_in[0];
    const float* qW = (const float*)d_in[1];
    const float* kW = (const float*)d_in[2];
    const float* vW = (const float*)d_in[3];
    const float* oW = (const float*)d_in[4];
    float* out = (float*)d_out;

    float *pq, *pk, *pv, *pctx;
    cudaGetSymbolAddress((void**)&pq, g_q);
    cudaGetSymbolAddress((void**)&pk, g_k);
    cudaGetSymbolAddress((void**)&pv, g_v);
    cudaGetSymbolAddress((void**)&pctx, g_ctx);

    cudaFuncSetAttribute(gemm_tf32, cudaFuncAttributeMaxDynamicSharedMemorySize, GSMEM);
    cudaFuncSetAttribute(flash_kernel, cudaFuncAttributeMaxDynamicSharedMemorySize, FSMEM);

    // Fused QKV projection: one launch, z = {q,k,v}
    dim3 ggridQKV(D_MODEL / TBN, MROWS / TBM, 3);   // (8, 32, 3) = 768 CTAs
    gemm_tf32<<<ggridQKV, 256, GSMEM>>>(x, qW, kW, vW, pq, pk, pv, 1);

    flash_kernel<<<dim3(SEQ / QT, BATCH * NH), 256, FSMEM>>>();

    dim3 ggridO(D_MODEL / TBN, MROWS / TBM, 1);     // (8, 32) = 256 CTAs
    gemm_tf32<<<ggridO, 256, GSMEM>>>(pctx, oW, oW, oW, out, out, out, 0);
}

// round 9
// speedup vs baseline: 1.4164x; 1.4164x over previous
#include <cuda_runtime.h>
#include <cuda_bf16.h>
#include <math.h>

#define D_MODEL 1024
#define NH 16
#define HD 64
#define BATCH 2
#define SEQ 2048
#define MROWS (BATCH*SEQ)

__device__ float g_q[BATCH*NH*SEQ*HD];
__device__ float g_k[BATCH*NH*SEQ*HD];
__device__ float g_v[BATCH*NH*SEQ*HD];
__device__ float g_ctx[MROWS*D_MODEL];

__device__ __forceinline__ unsigned f2tf(float x) {
    unsigned r;
    asm("cvt.rna.tf32.f32 %0, %1;" : "=r"(r) : "f"(x));
    return r;
}

__device__ __forceinline__ void mma8(float* c, uint4 a, uint2 b) {
    asm volatile(
        "mma.sync.aligned.m16n8k8.row.col.f32.tf32.tf32.f32 "
        "{%0,%1,%2,%3}, {%4,%5,%6,%7}, {%8,%9}, {%0,%1,%2,%3};"
        : "+f"(c[0]), "+f"(c[1]), "+f"(c[2]), "+f"(c[3])
        : "r"(a.x), "r"(a.y), "r"(a.z), "r"(a.w), "r"(b.x), "r"(b.y));
}

// A-layout: blk=(k/8)*8+(r/16) (512B); byte = lane'*16 + colhalf*8 + reg*4,
//   lane' = (r%8)*4 + k%4, regs (2c,2c+1) = rows (r, r+8). Swizzle ^(kb&3)<<4.
//   Read: LDS.128 at blk*512 + (lane*16 ^ (kb&3)<<4).
// B-layout: blk=(k/8)*NNB+(n/8) (256B); byte = ((n%8)*4 + k%4)*8 + reg*4,
//   regs (0,1) = (k, k+4). Swizzle ^(kb&3)<<3 (V: ^(n/8&7)<<3).
//   Read: LDS.64 at blk*256 + (lane*8 ^ sw).

// ============================================================================
// TF32 GEMM, fused over z: Y = X @ W^T. 8 warps (2x4), warp tile 64x32.
// Tile 128x128, K chunks of 32. Conflict-free STS.64 staging.
// ============================================================================
#define TBM 128
#define TBN 128
#define TBK 32
#define A_BYTES (TBM*TBK*4)
#define B_BYTES (TBN*TBK*4)
#define STG (A_BYTES + B_BYTES)
#define GSMEM (2*STG)            // 65536

__global__ __launch_bounds__(256, 2) void gemm_tf32(
    const float* __restrict__ X,
    const float* __restrict__ W0, const float* __restrict__ W1, const float* __restrict__ W2,
    float* __restrict__ Y0, float* __restrict__ Y1, float* __restrict__ Y2,
    int proj_mode)
{
    extern __shared__ char gsm[];
    const int tid = threadIdx.x;
    const int wid = tid >> 5, lane = tid & 31;
    const int g = lane >> 2, tq = lane & 3;
    const int wm = wid & 1, wn = wid >> 1;      // 2 x 4 warp grid
    const int bm = blockIdx.y * TBM, bn = blockIdx.x * TBN;
    const int z = blockIdx.z;
    const float* W = (z == 0) ? W0 : (z == 1) ? W1 : W2;
    float* Y = (z == 0) ? Y0 : (z == 1) ? Y1 : Y2;

    float acc[4][4][4];
    #pragma unroll
    for (int i = 0; i < 4; i++)
        #pragma unroll
        for (int j = 0; j < 4; j++)
            #pragma unroll
            for (int r = 0; r < 4; r++) acc[i][j][r] = 0.f;

    float4 pa[2][2], pb[2][2];
    auto ldregs = [&](int kt) {
        #pragma unroll
        for (int i = 0; i < 2; i++) {
            int u = i * 256 + tid;
            int kg = u & 7, rp = u >> 3, rl = rp & 7, mb = rp >> 3;
            const float* p = X + (size_t)(bm + mb * 16 + rl) * D_MODEL + kt + kg * 4;
            pa[i][0] = *(const float4*)p;
            pa[i][1] = *(const float4*)(p + 8 * D_MODEL);
            int kb = u & 3, n = u >> 2;
            const float* q = W + (size_t)(bn + n) * D_MODEL + kt + kb * 8;
            pb[i][0] = *(const float4*)q;
            pb[i][1] = *(const float4*)(q + 4);
        }
    };
    auto stg = [&](int buf) {
        char* Ab = gsm + buf * STG;
        char* Bb = Ab + A_BYTES;
        #pragma unroll
        for (int i = 0; i < 2; i++) {
            int u = i * 256 + tid;
            int kg = u & 7, rp = u >> 3, rl = rp & 7, mb = rp >> 3;
            int kb2 = kg >> 1, ch = kg & 1;
            unsigned base = (unsigned)((kb2 * 8 + mb) * 512 + ch * 8);
            const float *f0 = &pa[i][0].x, *f1 = &pa[i][1].x;
            #pragma unroll
            for (int j = 0; j < 4; j++) {
                unsigned off = (base + (unsigned)((rl * 4 + j) * 16)) ^ ((unsigned)kb2 << 4);
                uint2 v; v.x = f2tf(f0[j]); v.y = f2tf(f1[j]);
                *(uint2*)(Ab + off) = v;
            }
            int kb = u & 3, n = u >> 2;
            unsigned bbase = (unsigned)((kb * 16 + (n >> 3)) * 256);
            const float *h0 = &pb[i][0].x, *h1 = &pb[i][1].x;
            #pragma unroll
            for (int j = 0; j < 4; j++) {
                unsigned off = (bbase + (unsigned)(((n & 7) * 4 + j) * 8)) ^ ((unsigned)kb << 3);
                uint2 v; v.x = f2tf(h0[j]); v.y = f2tf(h1[j]);
                *(uint2*)(Bb + off) = v;
            }
        }
    };

    ldregs(0);
    const int NCH = D_MODEL / TBK;   // 32
    for (int j = 0; j < NCH; j++) {
        const int buf = j & 1;
        stg(buf);
        __syncthreads();
        if (j + 1 < NCH) ldregs((j + 1) * TBK);

        const char* Ab = gsm + buf * STG;
        const char* Bb = Ab + A_BYTES;
        #pragma unroll
        for (int kk8 = 0; kk8 < 4; kk8++) {
            const unsigned ax = ((unsigned)lane << 4) ^ ((unsigned)kk8 << 4);
            const unsigned bx = ((unsigned)lane << 3) ^ ((unsigned)kk8 << 3);
            uint4 a[4];
            #pragma unroll
            for (int mt = 0; mt < 4; mt++)
                a[mt] = *(const uint4*)(Ab + ((kk8 * 8 + wm * 4 + mt) << 9) + ax);
            uint2 b[4];
            #pragma unroll
            for (int nt = 0; nt < 4; nt++)
                b[nt] = *(const uint2*)(Bb + ((kk8 * 16 + wn * 4 + nt) << 8) + bx);
            #pragma unroll
            for (int mt = 0; mt < 4; mt++)
                #pragma unroll
                for (int nt = 0; nt < 4; nt++)
                    mma8(acc[mt][nt], a[mt], b[nt]);
        }
        __syncthreads();
    }

    #pragma unroll
    for (int mt = 0; mt < 4; mt++) {
        #pragma unroll
        for (int nt = 0; nt < 4; nt++) {
            int row0 = bm + wm * 64 + mt * 16 + g;
            int col = bn + wn * 32 + nt * 8 + tq * 2;
            #pragma unroll
            for (int hh2 = 0; hh2 < 2; hh2++) {
                int row = row0 + hh2 * 8;
                float v0 = acc[mt][nt][hh2 * 2 + 0];
                float v1 = acc[mt][nt][hh2 * 2 + 1];
                if (proj_mode) {
                    int b2 = row >> 11, s2 = row & (SEQ - 1);
                    int hh = col >> 6, d0 = col & 63;
                    float* dst = Y + ((size_t)((b2 * NH + hh) * SEQ + s2)) * HD + d0;
                    dst[0] = v0; dst[1] = v1;
                } else {
                    float* dst = Y + (size_t)row * D_MODEL + col;
                    dst[0] = v0; dst[1] = v1;
                }
            }
        }
    }
}

// ============================================================================
// Causal flash attention: 128-row Q tiles, 8 warps, 64-row KV tiles.
// All staging via swizzled STS.64; reads LDS.128/LDS.64 with matching XOR.
// ============================================================================
#define QT 128
#define KT 64
#define SQ_OFF 0
#define SK_OFF 32768
#define SV_OFF 49152
#define SP_OFF 65536
#define FSMEM 98304

__global__ __launch_bounds__(256, 2) void flash_kernel()
{
    extern __shared__ char smf[];
    char* Qb = smf + SQ_OFF;
    char* Kb = smf + SK_OFF;
    char* Vb = smf + SV_OFF;
    char* Pb = smf + SP_OFF;

    const int tid = threadIdx.x;
    const int w = tid >> 5, lane = tid & 31;
    const int g = lane >> 2, tq = lane & 3;
    const int bh = blockIdx.y;
    const int b = bh / NH, h = bh % NH;
    const int qt = (gridDim.x - 1 - blockIdx.x);   // heavy blocks first
    const int q0 = qt * QT;

    const float* qbase = g_q + (size_t)(b * NH + h) * SEQ * HD;
    const float* kbase = g_k + (size_t)(b * NH + h) * SEQ * HD;
    const float* vbase = g_v + (size_t)(b * NH + h) * SEQ * HD;

    // stage Q (128x64 A-layout), pre-scaled by 1/sqrt(HD)
    #pragma unroll
    for (int i = 0; i < 4; i++) {
        int u = i * 256 + tid;
        int kg = u & 15, rp = u >> 4, rl = rp & 7, mb = rp >> 3;
        int kb = kg >> 1, ch = kg & 1;
        const float* p = qbase + (size_t)(q0 + mb * 16 + rl) * HD + kg * 4;
        float4 v0 = *(const float4*)p;
        float4 v1 = *(const float4*)(p + 8 * HD);
        unsigned base = (unsigned)((kb * 8 + mb) * 512 + ch * 8);
        const float *f0 = &v0.x, *f1 = &v1.x;
        #pragma unroll
        for (int j = 0; j < 4; j++) {
            unsigned off = (base + (unsigned)((rl * 4 + j) * 16)) ^ ((unsigned)(kb & 3) << 4);
            uint2 vv; vv.x = f2tf(f0[j] * 0.125f); vv.y = f2tf(f1[j] * 0.125f);
            *(uint2*)(Qb + off) = vv;
        }
    }

    float o[8][4];
    #pragma unroll
    for (int nt = 0; nt < 8; nt++)
        #pragma unroll
        for (int r = 0; r < 4; r++) o[nt][r] = 0.f;
    float m0 = -INFINITY, m1 = -INFINITY, l0 = 0.f, l1 = 0.f;

    const int prow = w * 16 + g;
    const int row0g = q0 + prow;
    const int row1g = row0g + 8;
    // P store base (rows prow/prow+8, col = nt*8 + 2tq + {0,1})
    const unsigned pbase = (unsigned)((g * 4 + (tq & 1) * 2) * 16 + (tq >> 1) * 8);

    const int ktiles = 2 * qt + 2;
    for (int kt = 0; kt < ktiles; kt++) {
        const int kv0 = kt * KT;
        #pragma unroll
        for (int hf = 0; hf < 2; hf++) {
            int u = hf * 256 + tid;
            // K: B-layout NNB=8
            int kb = u & 7, n = u >> 3;
            const float* p = kbase + (size_t)(kv0 + n) * HD + kb * 8;
            float4 v0 = *(const float4*)p;
            float4 v1 = *(const float4*)(p + 4);
            unsigned base = (unsigned)((kb * 8 + (n >> 3)) * 256);
            const float *f0 = &v0.x, *f1 = &v1.x;
            #pragma unroll
            for (int j = 0; j < 4; j++) {
                unsigned off = (base + (unsigned)(((n & 7) * 4 + j) * 8)) ^ ((unsigned)(kb & 3) << 3);
                uint2 vv; vv.x = f2tf(f0[j]); vv.y = f2tf(f1[j]);
                *(uint2*)(Kb + off) = vv;
            }
            // V: transposed B-layout (n=d, k=kv), swizzle by d-block
            int dq = u & 15, rv = u >> 4;
            int rl4 = rv & 3, rkb = rv >> 2;
            int kv = rkb * 8 + rl4;
            const float* pv = vbase + (size_t)(kv0 + kv) * HD + dq * 4;
            float4 w0 = *(const float4*)pv;
            float4 w1 = *(const float4*)(pv + 4 * HD);
            const float *g0 = &w0.x, *g1 = &w1.x;
            #pragma unroll
            for (int j = 0; j < 4; j++) {
                int d = dq * 4 + j;
                unsigned off = ((unsigned)((rkb * 8 + (d >> 3)) * 256)
                              + (unsigned)(((d & 7) * 4 + rl4) * 8))
                             ^ (((unsigned)(d >> 3) & 7) << 3);
                uint2 vv; vv.x = f2tf(g0[j]); vv.y = f2tf(g1[j]);
                *(uint2*)(Vb + off) = vv;
            }
        }
        __syncthreads();

        // S = Q K^T
        float sc[8][4];
        #pragma unroll
        for (int nt = 0; nt < 8; nt++)
            #pragma unroll
            for (int r = 0; r < 4; r++) sc[nt][r] = 0.f;
        #pragma unroll
        for (int kk8 = 0; kk8 < 8; kk8++) {
            const unsigned ax = ((unsigned)lane << 4) ^ ((unsigned)(kk8 & 3) << 4);
            const unsigned bx = ((unsigned)lane << 3) ^ ((unsigned)(kk8 & 3) << 3);
            uint4 a = *(const uint4*)(Qb + ((kk8 * 8 + w) << 9) + ax);
            #pragma unroll
            for (int nt = 0; nt < 8; nt++) {
                uint2 bb = *(const uint2*)(Kb + ((kk8 * 8 + nt) << 8) + bx);
                mma8(sc[nt], a, bb);
            }
        }

        const bool msk0 = (kv0 + KT - 1 > row0g);
        const bool msk1 = (kv0 + KT - 1 > row1g);
        if (msk0 | msk1) {
            #pragma unroll
            for (int nt = 0; nt < 8; nt++) {
                int c0 = kv0 + nt * 8 + tq * 2;
                if (msk0) {
                    if (c0     > row0g) sc[nt][0] = -1e30f;
                    if (c0 + 1 > row0g) sc[nt][1] = -1e30f;
                }
                if (msk1) {
                    if (c0     > row1g) sc[nt][2] = -1e30f;
                    if (c0 + 1 > row1g) sc[nt][3] = -1e30f;
                }
            }
        }

        float rm0 = -1e30f, rm1 = -1e30f;
        #pragma unroll
        for (int nt = 0; nt < 8; nt++) {
            rm0 = fmaxf(rm0, fmaxf(sc[nt][0], sc[nt][1]));
            rm1 = fmaxf(rm1, fmaxf(sc[nt][2], sc[nt][3]));
        }
        rm0 = fmaxf(rm0, __shfl_xor_sync(0xffffffffu, rm0, 1));
        rm0 = fmaxf(rm0, __shfl_xor_sync(0xffffffffu, rm0, 2));
        rm1 = fmaxf(rm1, __shfl_xor_sync(0xffffffffu, rm1, 1));
        rm1 = fmaxf(rm1, __shfl_xor_sync(0xffffffffu, rm1, 2));

        float nm0 = fmaxf(m0, rm0), nm1 = fmaxf(m1, rm1);
        float a0 = __expf(m0 - nm0), a1 = __expf(m1 - nm1);
        m0 = nm0; m1 = nm1;

        float rs0 = 0.f, rs1 = 0.f;
        #pragma unroll
        for (int nt = 0; nt < 8; nt++) {
            float p0 = __expf(sc[nt][0] - nm0); sc[nt][0] = p0; rs0 += p0;
            float p1 = __expf(sc[nt][1] - nm0); sc[nt][1] = p1; rs0 += p1;
            float p2 = __expf(sc[nt][2] - nm1); sc[nt][2] = p2; rs1 += p2;
            float p3 = __expf(sc[nt][3] - nm1); sc[nt][3] = p3; rs1 += p3;
        }
        rs0 += __shfl_xor_sync(0xffffffffu, rs0, 1);
        rs0 += __shfl_xor_sync(0xffffffffu, rs0, 2);
        rs1 += __shfl_xor_sync(0xffffffffu, rs1, 1);
        rs1 += __shfl_xor_sync(0xffffffffu, rs1, 2);
        l0 = l0 * a0 + rs0;
        l1 = l1 * a1 + rs1;

        #pragma unroll
        for (int nt = 0; nt < 8; nt++) {
            o[nt][0] *= a0; o[nt][1] *= a0;
            o[nt][2] *= a1; o[nt][3] *= a1;
        }

        // P -> smem (A-layout, warp-private blocks nt*8+w), 2 STS.64 per nt
        #pragma unroll
        for (int nt = 0; nt < 8; nt++) {
            unsigned blkb = (unsigned)((nt * 8 + w) * 512);
            unsigned sw = ((unsigned)(nt & 3)) << 4;
            uint2 v0, v1;
            v0.x = f2tf(sc[nt][0]); v0.y = f2tf(sc[nt][2]);
            v1.x = f2tf(sc[nt][1]); v1.y = f2tf(sc[nt][3]);
            *(uint2*)(Pb + ((blkb + pbase) ^ sw)) = v0;
            *(uint2*)(Pb + ((blkb + pbase + 16) ^ sw)) = v1;
        }
        __syncwarp();

        // O += P V
        #pragma unroll
        for (int kk8 = 0; kk8 < 8; kk8++) {
            const unsigned ax = ((unsigned)lane << 4) ^ ((unsigned)(kk8 & 3) << 4);
            uint4 a = *(const uint4*)(Pb + ((kk8 * 8 + w) << 9) + ax);
            #pragma unroll
            for (int nt = 0; nt < 8; nt++) {
                unsigned bxv = ((unsigned)lane << 3) ^ (((unsigned)nt & 7) << 3);
                uint2 bb = *(const uint2*)(Vb + ((kk8 * 8 + nt) << 8) + bxv);
                mma8(o[nt], a, bb);
            }
        }
        __syncthreads();
    }

    float inv0 = 1.f / l0, inv1 = 1.f / l1;
    #pragma unroll
    for (int nt = 0; nt < 8; nt++) {
        int colg = h * HD + nt * 8 + tq * 2;
        size_t r0 = (size_t)(b * SEQ + row0g) * D_MODEL + colg;
        size_t r1 = (size_t)(b * SEQ + row1g) * D_MODEL + colg;
        g_ctx[r0]     = o[nt][0] * inv0;
        g_ctx[r0 + 1] = o[nt][1] * inv0;
        g_ctx[r1]     = o[nt][2] * inv1;
        g_ctx[r1 + 1] = o[nt][3] * inv1;
    }
}

// ============================================================================
extern "C" void kernel_launch(void* const* d_in, const int* in_sizes, int n_in,
                              void* d_out, int out_size)
{
    const float* x  = (const float*)d_in[0];
    const float* qW = (const float*)d_in[1];
    const float* kW = (const float*)d_in[2];
    const float* vW = (const float*)d_in[3];
    const float* oW = (const float*)d_in[4];
    float* out = (float*)d_out;

    float *pq, *pk, *pv, *pctx;
    cudaGetSymbolAddress((void**)&pq, g_q);
    cudaGetSymbolAddress((void**)&pk, g_k);
    cudaGetSymbolAddress((void**)&pv, g_v);
    cudaGetSymbolAddress((void**)&pctx, g_ctx);

    cudaFuncSetAttribute(gemm_tf32, cudaFuncAttributeMaxDynamicSharedMemorySize, GSMEM);
    cudaFuncSetAttribute(flash_kernel, cudaFuncAttributeMaxDynamicSharedMemorySize, FSMEM);

    dim3 ggridQKV(D_MODEL / TBN, MROWS / TBM, 3);   // (8, 32, 3)
    gemm_tf32<<<ggridQKV, 256, GSMEM>>>(x, qW, kW, vW, pq, pk, pv, 1);

    flash_kernel<<<dim3(SEQ / QT, BATCH * NH), 256, FSMEM>>>();

    dim3 ggridO(D_MODEL / TBN, MROWS / TBM, 1);     // (8, 32)
    gemm_tf32<<<ggridO, 256, GSMEM>>>(pctx, oW, oW, oW, out, out, out, 0);
}

// round 11
// speedup vs baseline: 1.6675x; 1.1773x over previous
#include <cuda_runtime.h>
#include <cuda_bf16.h>
#include <math.h>

#define D_MODEL 1024
#define NH 16
#define HD 64
#define BATCH 2
#define SEQ 2048
#define MROWS (BATCH*SEQ)

// Scratch
__device__ float g_q[BATCH*NH*SEQ*HD];
__device__ float g_k[BATCH*NH*SEQ*HD];
__device__ float g_v[BATCH*NH*SEQ*HD];
__device__ float g_ctx[MROWS*D_MODEL];
__device__ float g_xr[MROWS*D_MODEL];          // pre-rounded x
__device__ float g_wr[4*D_MODEL*D_MODEL];      // pre-rounded qW,kW,vW,oW

__device__ __forceinline__ unsigned f2tf(float x) {
    unsigned r;
    asm("cvt.rna.tf32.f32 %0, %1;" : "=r"(r) : "f"(x));
    return r;
}

__device__ __forceinline__ void mma8(float* c, uint4 a, uint2 b) {
    asm volatile(
        "mma.sync.aligned.m16n8k8.row.col.f32.tf32.tf32.f32 "
        "{%0,%1,%2,%3}, {%4,%5,%6,%7}, {%8,%9}, {%0,%1,%2,%3};"
        : "+f"(c[0]), "+f"(c[1]), "+f"(c[2]), "+f"(c[3])
        : "r"(a.x), "r"(a.y), "r"(a.z), "r"(a.w), "r"(b.x), "r"(b.y));
}

__device__ __forceinline__ uint4 ldsm4(unsigned a) {
    uint4 r;
    asm volatile("ldmatrix.sync.aligned.m8n8.x4.shared.b16 {%0,%1,%2,%3}, [%4];"
        : "=r"(r.x), "=r"(r.y), "=r"(r.z), "=r"(r.w) : "r"(a));
    return r;
}

__device__ __forceinline__ void cpa16(unsigned dst, const void* src) {
    asm volatile("cp.async.cg.shared.global [%0], [%1], 16;" :: "r"(dst), "l"(src));
}

// ============================================================================
// Prologue: round arrays to tf32 bits (values identical to f2tf-at-staging)
// ============================================================================
__global__ void round_tf32(const float4* s0, float4* d0,
                           const float4* s1, float4* d1,
                           const float4* s2, float4* d2,
                           const float4* s3, float4* d3,
                           const float4* s4, float4* d4)
{
    int z = blockIdx.y;
    const float4* s;
    float4* d;
    int n4;
    if (z == 0)      { s = s0; d = d0; n4 = MROWS * D_MODEL / 4; }
    else if (z == 1) { s = s1; d = d1; n4 = D_MODEL * D_MODEL / 4; }
    else if (z == 2) { s = s2; d = d2; n4 = D_MODEL * D_MODEL / 4; }
    else if (z == 3) { s = s3; d = d3; n4 = D_MODEL * D_MODEL / 4; }
    else             { s = s4; d = d4; n4 = D_MODEL * D_MODEL / 4; }
    for (int i = blockIdx.x * blockDim.x + threadIdx.x; i < n4;
         i += gridDim.x * blockDim.x) {
        float4 v = s[i];
        float4 r;
        r.x = __uint_as_float(f2tf(v.x));
        r.y = __uint_as_float(f2tf(v.y));
        r.z = __uint_as_float(f2tf(v.z));
        r.w = __uint_as_float(f2tf(v.w));
        d[i] = r;
    }
}

// ============================================================================
// TF32 GEMM: cp.async 3-stage -> row-major smem (stride 36 fl) -> ldmatrix.
// 8 warps (2x4), warp tile 64x32, block tile 128x128, K chunks of 32.
// Inputs MUST be pre-rounded tf32 bits.
// ============================================================================
#define TBM 128
#define TBN 128
#define TBK 32
#define RST 144                 // row stride bytes (36 floats); 36r mod 32 distinct -> LDSM cf
#define TILE_B (128*RST)        // 18432
#define STAGE_B (2*TILE_B)      // 36864
#define GSMEM (3*STAGE_B)       // 110592

__global__ __launch_bounds__(256, 2) void gemm_tc(
    const float* __restrict__ X,
    const float* __restrict__ W0, const float* __restrict__ W1, const float* __restrict__ W2,
    float* __restrict__ Y0, float* __restrict__ Y1, float* __restrict__ Y2,
    int proj_mode)
{
    extern __shared__ char gsm[];
    const unsigned sbase = (unsigned)__cvta_generic_to_shared(gsm);
    const int tid = threadIdx.x;
    const int wid = tid >> 5, lane = tid & 31;
    const int g = lane >> 2, tq = lane & 3;
    const int wm = wid & 1, wn = wid >> 1;      // 2 x 4 warp grid
    const int bm = blockIdx.y * TBM, bn = blockIdx.x * TBN;
    const int z = blockIdx.z;
    const float* W = (z == 0) ? W0 : (z == 1) ? W1 : W2;
    float* Y = (z == 0) ? Y0 : (z == 1) ? Y1 : Y2;

    float acc[4][4][4];
    #pragma unroll
    for (int i = 0; i < 4; i++)
        #pragma unroll
        for (int j = 0; j < 4; j++)
            #pragma unroll
            for (int r = 0; r < 4; r++) acc[i][j][r] = 0.f;

    // loader: unit c = t*256+tid -> row=c>>3 (0..127), k16=c&7
    auto stage = [&](int j, int s) {
        const int kt = j * TBK;
        unsigned ab = sbase + (unsigned)s * STAGE_B;
        unsigned bb = ab + TILE_B;
        #pragma unroll
        for (int t = 0; t < 4; t++) {
            int c = t * 256 + tid, row = c >> 3, k16 = c & 7;
            cpa16(ab + row * RST + k16 * 16,
                  X + (size_t)(bm + row) * D_MODEL + kt + k16 * 4);
            cpa16(bb + row * RST + k16 * 16,
                  W + (size_t)(bn + row) * D_MODEL + kt + k16 * 4);
        }
        asm volatile("cp.async.commit_group;");
    };

    // per-lane LDSM offsets
    const unsigned laneOffA = (unsigned)(((lane & 7) + ((lane >> 3) & 1) * 8) * RST
                            + ((lane >> 4) & 1) * 16);
    const unsigned laneOffB = (unsigned)((((lane >> 4) & 1) * 8 + (lane & 7)) * RST
                            + ((lane >> 3) & 1) * 16);

    stage(0, 0);
    stage(1, 1);
    const int NCH = D_MODEL / TBK;   // 32
    for (int j = 0; j < NCH; j++) {
        if (j < NCH - 1) asm volatile("cp.async.wait_group 1;");
        else             asm volatile("cp.async.wait_group 0;");
        __syncthreads();
        if (j + 2 < NCH) stage(j + 2, (j + 2) % 3);

        unsigned ab = sbase + (unsigned)(j % 3) * STAGE_B;
        unsigned bb = ab + TILE_B;
        const unsigned awBase = ab + (unsigned)(wm * 64) * RST + laneOffA;
        const unsigned bwBase = bb + (unsigned)(wn * 32) * RST + laneOffB;
        #pragma unroll
        for (int kk8 = 0; kk8 < 4; kk8++) {
            uint4 a[4];
            #pragma unroll
            for (int mt = 0; mt < 4; mt++)
                a[mt] = ldsm4(awBase + (unsigned)(mt * 16) * RST + kk8 * 32);
            uint4 b0 = ldsm4(bwBase + kk8 * 32);                        // nt 0,1
            uint4 b1 = ldsm4(bwBase + (unsigned)(16 * RST) + kk8 * 32); // nt 2,3
            uint2 bf[4];
            bf[0] = make_uint2(b0.x, b0.y);
            bf[1] = make_uint2(b0.z, b0.w);
            bf[2] = make_uint2(b1.x, b1.y);
            bf[3] = make_uint2(b1.z, b1.w);
            #pragma unroll
            for (int mt = 0; mt < 4; mt++)
                #pragma unroll
                for (int nt = 0; nt < 4; nt++)
                    mma8(acc[mt][nt], a[mt], bf[nt]);
        }
        __syncthreads();
    }

    #pragma unroll
    for (int mt = 0; mt < 4; mt++) {
        #pragma unroll
        for (int nt = 0; nt < 4; nt++) {
            int row0 = bm + wm * 64 + mt * 16 + g;
            int col = bn + wn * 32 + nt * 8 + tq * 2;
            #pragma unroll
            for (int hh2 = 0; hh2 < 2; hh2++) {
                int row = row0 + hh2 * 8;
                float v0 = acc[mt][nt][hh2 * 2 + 0];
                float v1 = acc[mt][nt][hh2 * 2 + 1];
                if (proj_mode) {
                    int b2 = row >> 11, s2 = row & (SEQ - 1);
                    int hh = col >> 6, d0 = col & 63;
                    float* dst = Y + ((size_t)((b2 * NH + hh) * SEQ + s2)) * HD + d0;
                    dst[0] = v0; dst[1] = v1;
                } else {
                    float* dst = Y + (size_t)row * D_MODEL + col;
                    dst[0] = v0; dst[1] = v1;
                }
            }
        }
    }
}

// ============================================================================
// Causal flash attention (R9, unchanged except rounded ctx epilogue).
// ============================================================================
#define QT 128
#define KT 64
#define SQ_OFF 0
#define SK_OFF 32768
#define SV_OFF 49152
#define SP_OFF 65536
#define FSMEM 98304

__global__ __launch_bounds__(256, 2) void flash_kernel()
{
    extern __shared__ char smf[];
    char* Qb = smf + SQ_OFF;
    char* Kb = smf + SK_OFF;
    char* Vb = smf + SV_OFF;
    char* Pb = smf + SP_OFF;

    const int tid = threadIdx.x;
    const int w = tid >> 5, lane = tid & 31;
    const int g = lane >> 2, tq = lane & 3;
    const int bh = blockIdx.y;
    const int b = bh / NH, h = bh % NH;
    const int qt = (gridDim.x - 1 - blockIdx.x);
    const int q0 = qt * QT;

    const float* qbase = g_q + (size_t)(b * NH + h) * SEQ * HD;
    const float* kbase = g_k + (size_t)(b * NH + h) * SEQ * HD;
    const float* vbase = g_v + (size_t)(b * NH + h) * SEQ * HD;

    #pragma unroll
    for (int i = 0; i < 4; i++) {
        int u = i * 256 + tid;
        int kg = u & 15, rp = u >> 4, rl = rp & 7, mb = rp >> 3;
        int kb = kg >> 1, ch = kg & 1;
        const float* p = qbase + (size_t)(q0 + mb * 16 + rl) * HD + kg * 4;
        float4 v0 = *(const float4*)p;
        float4 v1 = *(const float4*)(p + 8 * HD);
        unsigned base = (unsigned)((kb * 8 + mb) * 512 + ch * 8);
        const float *f0 = &v0.x, *f1 = &v1.x;
        #pragma unroll
        for (int j = 0; j < 4; j++) {
            unsigned off = (base + (unsigned)((rl * 4 + j) * 16)) ^ ((unsigned)(kb & 3) << 4);
            uint2 vv; vv.x = f2tf(f0[j] * 0.125f); vv.y = f2tf(f1[j] * 0.125f);
            *(uint2*)(Qb + off) = vv;
        }
    }

    float o[8][4];
    #pragma unroll
    for (int nt = 0; nt < 8; nt++)
        #pragma unroll
        for (int r = 0; r < 4; r++) o[nt][r] = 0.f;
    float m0 = -INFINITY, m1 = -INFINITY, l0 = 0.f, l1 = 0.f;

    const int prow = w * 16 + g;
    const int row0g = q0 + prow;
    const int row1g = row0g + 8;
    const unsigned pbase = (unsigned)((g * 4 + (tq & 1) * 2) * 16 + (tq >> 1) * 8);

    const int ktiles = 2 * qt + 2;
    for (int kt = 0; kt < ktiles; kt++) {
        const int kv0 = kt * KT;
        #pragma unroll
        for (int hf = 0; hf < 2; hf++) {
            int u = hf * 256 + tid;
            int kb = u & 7, n = u >> 3;
            const float* p = kbase + (size_t)(kv0 + n) * HD + kb * 8;
            float4 v0 = *(const float4*)p;
            float4 v1 = *(const float4*)(p + 4);
            unsigned base = (unsigned)((kb * 8 + (n >> 3)) * 256);
            const float *f0 = &v0.x, *f1 = &v1.x;
            #pragma unroll
            for (int j = 0; j < 4; j++) {
                unsigned off = (base + (unsigned)(((n & 7) * 4 + j) * 8)) ^ ((unsigned)(kb & 3) << 3);
                uint2 vv; vv.x = f2tf(f0[j]); vv.y = f2tf(f1[j]);
                *(uint2*)(Kb + off) = vv;
            }
            int dq = u & 15, rv = u >> 4;
            int rl4 = rv & 3, rkb = rv >> 2;
            int kv = rkb * 8 + rl4;
            const float* pv = vbase + (size_t)(kv0 + kv) * HD + dq * 4;
            float4 w0 = *(const float4*)pv;
            float4 w1 = *(const float4*)(pv + 4 * HD);
            const float *g0 = &w0.x, *g1 = &w1.x;
            #pragma unroll
            for (int j = 0; j < 4; j++) {
                int d = dq * 4 + j;
                unsigned off = ((unsigned)((rkb * 8 + (d >> 3)) * 256)
                              + (unsigned)(((d & 7) * 4 + rl4) * 8))
                             ^ (((unsigned)(d >> 3) & 7) << 3);
                uint2 vv; vv.x = f2tf(g0[j]); vv.y = f2tf(g1[j]);
                *(uint2*)(Vb + off) = vv;
            }
        }
        __syncthreads();

        float sc[8][4];
        #pragma unroll
        for (int nt = 0; nt < 8; nt++)
            #pragma unroll
            for (int r = 0; r < 4; r++) sc[nt][r] = 0.f;
        #pragma unroll
        for (int kk8 = 0; kk8 < 8; kk8++) {
            const unsigned ax = ((unsigned)lane << 4) ^ ((unsigned)(kk8 & 3) << 4);
            const unsigned bx = ((unsigned)lane << 3) ^ ((unsigned)(kk8 & 3) << 3);
            uint4 a = *(const uint4*)(Qb + ((kk8 * 8 + w) << 9) + ax);
            #pragma unroll
            for (int nt = 0; nt < 8; nt++) {
                uint2 bb = *(const uint2*)(Kb + ((kk8 * 8 + nt) << 8) + bx);
                mma8(sc[nt], a, bb);
            }
        }

        const bool msk0 = (kv0 + KT - 1 > row0g);
        const bool msk1 = (kv0 + KT - 1 > row1g);
        if (msk0 | msk1) {
            #pragma unroll
            for (int nt = 0; nt < 8; nt++) {
                int c0 = kv0 + nt * 8 + tq * 2;
                if (msk0) {
                    if (c0     > row0g) sc[nt][0] = -1e30f;
                    if (c0 + 1 > row0g) sc[nt][1] = -1e30f;
                }
                if (msk1) {
                    if (c0     > row1g) sc[nt][2] = -1e30f;
                    if (c0 + 1 > row1g) sc[nt][3] = -1e30f;
                }
            }
        }

        float rm0 = -1e30f, rm1 = -1e30f;
        #pragma unroll
        for (int nt = 0; nt < 8; nt++) {
            rm0 = fmaxf(rm0, fmaxf(sc[nt][0], sc[nt][1]));
            rm1 = fmaxf(rm1, fmaxf(sc[nt][2], sc[nt][3]));
        }
        rm0 = fmaxf(rm0, __shfl_xor_sync(0xffffffffu, rm0, 1));
        rm0 = fmaxf(rm0, __shfl_xor_sync(0xffffffffu, rm0, 2));
        rm1 = fmaxf(rm1, __shfl_xor_sync(0xffffffffu, rm1, 1));
        rm1 = fmaxf(rm1, __shfl_xor_sync(0xffffffffu, rm1, 2));

        float nm0 = fmaxf(m0, rm0), nm1 = fmaxf(m1, rm1);
        float a0 = __expf(m0 - nm0), a1 = __expf(m1 - nm1);
        m0 = nm0; m1 = nm1;

        float rs0 = 0.f, rs1 = 0.f;
        #pragma unroll
        for (int nt = 0; nt < 8; nt++) {
            float p0 = __expf(sc[nt][0] - nm0); sc[nt][0] = p0; rs0 += p0;
            float p1 = __expf(sc[nt][1] - nm0); sc[nt][1] = p1; rs0 += p1;
            float p2 = __expf(sc[nt][2] - nm1); sc[nt][2] = p2; rs1 += p2;
            float p3 = __expf(sc[nt][3] - nm1); sc[nt][3] = p3; rs1 += p3;
        }
        rs0 += __shfl_xor_sync(0xffffffffu, rs0, 1);
        rs0 += __shfl_xor_sync(0xffffffffu, rs0, 2);
        rs1 += __shfl_xor_sync(0xffffffffu, rs1, 1);
        rs1 += __shfl_xor_sync(0xffffffffu, rs1, 2);
        l0 = l0 * a0 + rs0;
        l1 = l1 * a1 + rs1;

        #pragma unroll
        for (int nt = 0; nt < 8; nt++) {
            o[nt][0] *= a0; o[nt][1] *= a0;
            o[nt][2] *= a1; o[nt][3] *= a1;
        }

        #pragma unroll
        for (int nt = 0; nt < 8; nt++) {
            unsigned blkb = (unsigned)((nt * 8 + w) * 512);
            unsigned sw = ((unsigned)(nt & 3)) << 4;
            uint2 v0, v1;
            v0.x = f2tf(sc[nt][0]); v0.y = f2tf(sc[nt][2]);
            v1.x = f2tf(sc[nt][1]); v1.y = f2tf(sc[nt][3]);
            *(uint2*)(Pb + ((blkb + pbase) ^ sw)) = v0;
            *(uint2*)(Pb + ((blkb + pbase + 16) ^ sw)) = v1;
        }
        __syncwarp();

        #pragma unroll
        for (int kk8 = 0; kk8 < 8; kk8++) {
            const unsigned ax = ((unsigned)lane << 4) ^ ((unsigned)(kk8 & 3) << 4);
            uint4 a = *(const uint4*)(Pb + ((kk8 * 8 + w) << 9) + ax);
            #pragma unroll
            for (int nt = 0; nt < 8; nt++) {
                unsigned bxv = ((unsigned)lane << 3) ^ (((unsigned)nt & 7) << 3);
                uint2 bb = *(const uint2*)(Vb + ((kk8 * 8 + nt) << 8) + bxv);
                mma8(o[nt], a, bb);
            }
        }
        __syncthreads();
    }

    // epilogue: normalize, pre-round, write ctx (feeds pre-rounded O-proj GEMM)
    float inv0 = 1.f / l0, inv1 = 1.f / l1;
    #pragma unroll
    for (int nt = 0; nt < 8; nt++) {
        int colg = h * HD + nt * 8 + tq * 2;
        size_t r0 = (size_t)(b * SEQ + row0g) * D_MODEL + colg;
        size_t r1 = (size_t)(b * SEQ + row1g) * D_MODEL + colg;
        g_ctx[r0]     = __uint_as_float(f2tf(o[nt][0] * inv0));
        g_ctx[r0 + 1] = __uint_as_float(f2tf(o[nt][1] * inv0));
        g_ctx[r1]     = __uint_as_float(f2tf(o[nt][2] * inv1));
        g_ctx[r1 + 1] = __uint_as_float(f2tf(o[nt][3] * inv1));
    }
}

// ============================================================================
extern "C" void kernel_launch(void* const* d_in, const int* in_sizes, int n_in,
                              void* d_out, int out_size)
{
    const float* x  = (const float*)d_in[0];
    const float* qW = (const float*)d_in[1];
    const float* kW = (const float*)d_in[2];
    const float* vW = (const float*)d_in[3];
    const float* oW = (const float*)d_in[4];
    float* out = (float*)d_out;

    float *pq, *pk, *pv, *pctx, *pxr, *pwr;
    cudaGetSymbolAddress((void**)&pq, g_q);
    cudaGetSymbolAddress((void**)&pk, g_k);
    cudaGetSymbolAddress((void**)&pv, g_v);
    cudaGetSymbolAddress((void**)&pctx, g_ctx);
    cudaGetSymbolAddress((void**)&pxr, g_xr);
    cudaGetSymbolAddress((void**)&pwr, g_wr);
    float* pw0 = pwr;
    float* pw1 = pwr + D_MODEL * D_MODEL;
    float* pw2 = pwr + 2 * D_MODEL * D_MODEL;
    float* pw3 = pwr + 3 * D_MODEL * D_MODEL;

    cudaFuncSetAttribute(gemm_tc, cudaFuncAttributeMaxDynamicSharedMemorySize, GSMEM);
    cudaFuncSetAttribute(flash_kernel, cudaFuncAttributeMaxDynamicSharedMemorySize, FSMEM);

    // Prologue: pre-round x and all weights to tf32 bits
    round_tf32<<<dim3(512, 5), 256>>>(
        (const float4*)x,  (float4*)pxr,
        (const float4*)qW, (float4*)pw0,
        (const float4*)kW, (float4*)pw1,
        (const float4*)vW, (float4*)pw2,
        (const float4*)oW, (float4*)pw3);

    // Fused QKV projection
    dim3 ggridQKV(D_MODEL / TBN, MROWS / TBM, 3);   // (8, 32, 3)
    gemm_tc<<<ggridQKV, 256, GSMEM>>>(pxr, pw0, pw1, pw2, pq, pk, pv, 1);

    flash_kernel<<<dim3(SEQ / QT, BATCH * NH), 256, FSMEM>>>();

    dim3 ggridO(D_MODEL / TBN, MROWS / TBM, 1);     // (8, 32)
    gemm_tc<<<ggridO, 256, GSMEM>>>(pctx, pw3, pw3, pw3, out, out, out, 0);
}

// round 12
// speedup vs baseline: 1.7447x; 1.0463x over previous
#include <cuda_runtime.h>
#include <cuda_bf16.h>
#include <math.h>

#define D_MODEL 1024
#define NH 16
#define HD 64
#define BATCH 2
#define SEQ 2048
#define MROWS (BATCH*SEQ)

// Scratch. q: pre-scaled(1/8)+tf32-rounded [B,H,S,HD]. k: rounded [B,H,S,HD].
// v: rounded TRANSPOSED [B,H,HD,S]. ctx: rounded [B*S, D_MODEL].
__device__ float g_q[BATCH*NH*SEQ*HD];
__device__ float g_k[BATCH*NH*SEQ*HD];
__device__ float g_v[BATCH*NH*SEQ*HD];
__device__ float g_ctx[MROWS*D_MODEL];
__device__ float g_xr[MROWS*D_MODEL];
__device__ float g_wr[4*D_MODEL*D_MODEL];

__device__ __forceinline__ unsigned f2tf(float x) {
    unsigned r;
    asm("cvt.rna.tf32.f32 %0, %1;" : "=r"(r) : "f"(x));
    return r;
}

__device__ __forceinline__ void mma8(float* c, uint4 a, uint2 b) {
    asm volatile(
        "mma.sync.aligned.m16n8k8.row.col.f32.tf32.tf32.f32 "
        "{%0,%1,%2,%3}, {%4,%5,%6,%7}, {%8,%9}, {%0,%1,%2,%3};"
        : "+f"(c[0]), "+f"(c[1]), "+f"(c[2]), "+f"(c[3])
        : "r"(a.x), "r"(a.y), "r"(a.z), "r"(a.w), "r"(b.x), "r"(b.y));
}

__device__ __forceinline__ uint4 ldsm4(unsigned a) {
    uint4 r;
    asm volatile("ldmatrix.sync.aligned.m8n8.x4.shared.b16 {%0,%1,%2,%3}, [%4];"
        : "=r"(r.x), "=r"(r.y), "=r"(r.z), "=r"(r.w) : "r"(a));
    return r;
}

__device__ __forceinline__ void cpa16(unsigned dst, const void* src) {
    asm volatile("cp.async.cg.shared.global [%0], [%1], 16;" :: "r"(dst), "l"(src));
}

// ============================================================================
// Prologue: round x and weights to tf32 bits
// ============================================================================
__global__ void round_tf32(const float4* s0, float4* d0,
                           const float4* s1, float4* d1,
                           const float4* s2, float4* d2,
                           const float4* s3, float4* d3,
                           const float4* s4, float4* d4)
{
    int z = blockIdx.y;
    const float4* s;
    float4* d;
    int n4;
    if (z == 0)      { s = s0; d = d0; n4 = MROWS * D_MODEL / 4; }
    else if (z == 1) { s = s1; d = d1; n4 = D_MODEL * D_MODEL / 4; }
    else if (z == 2) { s = s2; d = d2; n4 = D_MODEL * D_MODEL / 4; }
    else if (z == 3) { s = s3; d = d3; n4 = D_MODEL * D_MODEL / 4; }
    else             { s = s4; d = d4; n4 = D_MODEL * D_MODEL / 4; }
    for (int i = blockIdx.x * blockDim.x + threadIdx.x; i < n4;
         i += gridDim.x * blockDim.x) {
        float4 v = s[i];
        float4 r;
        r.x = __uint_as_float(f2tf(v.x));
        r.y = __uint_as_float(f2tf(v.y));
        r.z = __uint_as_float(f2tf(v.z));
        r.w = __uint_as_float(f2tf(v.w));
        d[i] = r;
    }
}

// ============================================================================
// TF32 GEMM: cp.async 3-stage -> row-major smem (144B rows) -> ldmatrix.
// proj_mode=1: z=0 -> q (scale+round), z=1 -> k (round), z=2 -> v (round,
// transposed scatter). proj_mode=0: plain fp32 out.
// ============================================================================
#define TBM 128
#define TBN 128
#define TBK 32
#define RST 144
#define TILE_B (128*RST)
#define STAGE_B (2*TILE_B)
#define GSMEM (3*STAGE_B)       // 110592

__global__ __launch_bounds__(256, 2) void gemm_tc(
    const float* __restrict__ X,
    const float* __restrict__ W0, const float* __restrict__ W1, const float* __restrict__ W2,
    float* __restrict__ Y0, float* __restrict__ Y1, float* __restrict__ Y2,
    int proj_mode)
{
    extern __shared__ char gsm[];
    const unsigned sbase = (unsigned)__cvta_generic_to_shared(gsm);
    const int tid = threadIdx.x;
    const int wid = tid >> 5, lane = tid & 31;
    const int g = lane >> 2, tq = lane & 3;
    const int wm = wid & 1, wn = wid >> 1;
    const int bm = blockIdx.y * TBM, bn = blockIdx.x * TBN;
    const int z = blockIdx.z;
    const float* W = (z == 0) ? W0 : (z == 1) ? W1 : W2;
    float* Y = (z == 0) ? Y0 : (z == 1) ? Y1 : Y2;

    float acc[4][4][4];
    #pragma unroll
    for (int i = 0; i < 4; i++)
        #pragma unroll
        for (int j = 0; j < 4; j++)
            #pragma unroll
            for (int r = 0; r < 4; r++) acc[i][j][r] = 0.f;

    auto stage = [&](int j, int s) {
        const int kt = j * TBK;
        unsigned ab = sbase + (unsigned)s * STAGE_B;
        unsigned bb = ab + TILE_B;
        #pragma unroll
        for (int t = 0; t < 4; t++) {
            int c = t * 256 + tid, row = c >> 3, k16 = c & 7;
            cpa16(ab + row * RST + k16 * 16,
                  X + (size_t)(bm + row) * D_MODEL + kt + k16 * 4);
            cpa16(bb + row * RST + k16 * 16,
                  W + (size_t)(bn + row) * D_MODEL + kt + k16 * 4);
        }
        asm volatile("cp.async.commit_group;");
    };

    const unsigned laneOffA = (unsigned)(((lane & 7) + ((lane >> 3) & 1) * 8) * RST
                            + ((lane >> 4) & 1) * 16);
    const unsigned laneOffB = (unsigned)((((lane >> 4) & 1) * 8 + (lane & 7)) * RST
                            + ((lane >> 3) & 1) * 16);

    stage(0, 0);
    stage(1, 1);
    const int NCH = D_MODEL / TBK;
    for (int j = 0; j < NCH; j++) {
        if (j < NCH - 1) asm volatile("cp.async.wait_group 1;");
        else             asm volatile("cp.async.wait_group 0;");
        __syncthreads();
        if (j + 2 < NCH) stage(j + 2, (j + 2) % 3);

        unsigned ab = sbase + (unsigned)(j % 3) * STAGE_B;
        unsigned bb = ab + TILE_B;
        const unsigned awBase = ab + (unsigned)(wm * 64) * RST + laneOffA;
        const unsigned bwBase = bb + (unsigned)(wn * 32) * RST + laneOffB;
        #pragma unroll
        for (int kk8 = 0; kk8 < 4; kk8++) {
            uint4 a[4];
            #pragma unroll
            for (int mt = 0; mt < 4; mt++)
                a[mt] = ldsm4(awBase + (unsigned)(mt * 16) * RST + kk8 * 32);
            uint4 b0 = ldsm4(bwBase + kk8 * 32);
            uint4 b1 = ldsm4(bwBase + (unsigned)(16 * RST) + kk8 * 32);
            uint2 bf[4];
            bf[0] = make_uint2(b0.x, b0.y);
            bf[1] = make_uint2(b0.z, b0.w);
            bf[2] = make_uint2(b1.x, b1.y);
            bf[3] = make_uint2(b1.z, b1.w);
            #pragma unroll
            for (int mt = 0; mt < 4; mt++)
                #pragma unroll
                for (int nt = 0; nt < 4; nt++)
                    mma8(acc[mt][nt], a[mt], bf[nt]);
        }
        __syncthreads();
    }

    #pragma unroll
    for (int mt = 0; mt < 4; mt++) {
        #pragma unroll
        for (int nt = 0; nt < 4; nt++) {
            int row0 = bm + wm * 64 + mt * 16 + g;
            int col = bn + wn * 32 + nt * 8 + tq * 2;
            #pragma unroll
            for (int hh2 = 0; hh2 < 2; hh2++) {
                int row = row0 + hh2 * 8;
                float v0 = acc[mt][nt][hh2 * 2 + 0];
                float v1 = acc[mt][nt][hh2 * 2 + 1];
                if (proj_mode) {
                    int b2 = row >> 11, s2 = row & (SEQ - 1);
                    int hh = col >> 6, d0 = col & 63;
                    float r0, r1;
                    if (z == 0) {            // q: pre-scale by 1/sqrt(64), round
                        r0 = __uint_as_float(f2tf(v0 * 0.125f));
                        r1 = __uint_as_float(f2tf(v1 * 0.125f));
                    } else {                 // k, v: round
                        r0 = __uint_as_float(f2tf(v0));
                        r1 = __uint_as_float(f2tf(v1));
                    }
                    if (z == 2) {            // v: transposed [B,H,HD,S]
                        float* dst = Y + ((size_t)((b2 * NH + hh) * HD + d0)) * SEQ + s2;
                        dst[0] = r0; dst[SEQ] = r1;
                    } else {
                        float* dst = Y + ((size_t)((b2 * NH + hh) * SEQ + s2)) * HD + d0;
                        dst[0] = r0; dst[1] = r1;
                    }
                } else {
                    float* dst = Y + (size_t)row * D_MODEL + col;
                    dst[0] = v0; dst[1] = v1;
                }
            }
        }
    }
}

// ============================================================================
// Causal flash attention: cp.async + ldmatrix for Q/K/V^T; P via swizzled
// A-layout (R9 path). 128-row Q tiles, 8 warps, 64-row KV tiles.
// Row-major smem stride 272B (17 units mod 32 distinct -> LDSM conflict-free).
// ============================================================================
#define QT 128
#define KT 64
#define QST2 272
#define SQ_OFF 0                           // 128*272 = 34816
#define SK_OFF 34816                       // 64*272 = 17408
#define SV_OFF 52224                       // 64*272 = 17408
#define SP_OFF 69632                       // P A-layout, 32768
#define FSMEM 102400

__global__ __launch_bounds__(256, 2) void flash_kernel()
{
    extern __shared__ char smf[];
    const unsigned sbase = (unsigned)__cvta_generic_to_shared(smf);
    char* Pb = smf + SP_OFF;

    const int tid = threadIdx.x;
    const int w = tid >> 5, lane = tid & 31;
    const int g = lane >> 2, tq = lane & 3;
    const int bh = blockIdx.y;
    const int b = bh / NH, h = bh % NH;
    const int qt = (gridDim.x - 1 - blockIdx.x);
    const int q0 = qt * QT;

    const float* qbase = g_q + (size_t)(b * NH + h) * SEQ * HD + (size_t)q0 * HD;
    const float* kbase = g_k + (size_t)(b * NH + h) * SEQ * HD;
    const float* vtb   = g_v + (size_t)(b * NH + h) * SEQ * HD;   // [HD][SEQ]

    // stage Q (128 x 64 fl, rows stride 272B)
    #pragma unroll
    for (int i = 0; i < 8; i++) {
        int u = i * 256 + tid, row = u >> 4, k16 = u & 15;
        cpa16(sbase + SQ_OFF + row * QST2 + k16 * 16, qbase + row * HD + k16 * 4);
    }
    asm volatile("cp.async.commit_group;");

    float o[8][4];
    #pragma unroll
    for (int nt = 0; nt < 8; nt++)
        #pragma unroll
        for (int r = 0; r < 4; r++) o[nt][r] = 0.f;
    float m0 = -INFINITY, m1 = -INFINITY, l0 = 0.f, l1 = 0.f;

    const int prow = w * 16 + g;
    const int row0g = q0 + prow;
    const int row1g = row0g + 8;
    const unsigned pbase = (unsigned)((g * 4 + (tq & 1) * 2) * 16 + (tq >> 1) * 8);

    const unsigned laneOffA = (unsigned)(((lane & 7) + ((lane >> 3) & 1) * 8) * QST2
                            + ((lane >> 4) & 1) * 16);
    const unsigned laneOffB = (unsigned)((((lane >> 4) & 1) * 8 + (lane & 7)) * QST2
                            + ((lane >> 3) & 1) * 16);
    const unsigned awQ = sbase + SQ_OFF + (unsigned)(w * 16) * QST2 + laneOffA;
    const unsigned bwK = sbase + SK_OFF + laneOffB;
    const unsigned bwV = sbase + SV_OFF + laneOffB;

    const int ktiles = 2 * qt + 2;
    for (int kt = 0; kt < ktiles; kt++) {
        const int kv0 = kt * KT;
        // stage K (64 x 64) and V^T (64 d-rows x 64 kv)
        #pragma unroll
        for (int i = 0; i < 4; i++) {
            int u = i * 256 + tid, row = u >> 4, k16 = u & 15;
            cpa16(sbase + SK_OFF + row * QST2 + k16 * 16,
                  kbase + (size_t)(kv0 + row) * HD + k16 * 4);
            cpa16(sbase + SV_OFF + row * QST2 + k16 * 16,
                  vtb + (size_t)row * SEQ + kv0 + k16 * 4);
        }
        asm volatile("cp.async.commit_group;");
        asm volatile("cp.async.wait_group 0;");
        __syncthreads();

        // S = Q K^T
        float sc[8][4];
        #pragma unroll
        for (int nt = 0; nt < 8; nt++)
            #pragma unroll
            for (int r = 0; r < 4; r++) sc[nt][r] = 0.f;
        #pragma unroll
        for (int kk8 = 0; kk8 < 8; kk8++) {
            uint4 a = ldsm4(awQ + kk8 * 32);
            #pragma unroll
            for (int i = 0; i < 4; i++) {
                uint4 bq = ldsm4(bwK + (unsigned)(i * 16) * QST2 + kk8 * 32);
                mma8(sc[2 * i + 0], a, make_uint2(bq.x, bq.y));
                mma8(sc[2 * i + 1], a, make_uint2(bq.z, bq.w));
            }
        }

        const bool msk0 = (kv0 + KT - 1 > row0g);
        const bool msk1 = (kv0 + KT - 1 > row1g);
        if (msk0 | msk1) {
            #pragma unroll
            for (int nt = 0; nt < 8; nt++) {
                int c0 = kv0 + nt * 8 + tq * 2;
                if (msk0) {
                    if (c0     > row0g) sc[nt][0] = -1e30f;
                    if (c0 + 1 > row0g) sc[nt][1] = -1e30f;
                }
                if (msk1) {
                    if (c0     > row1g) sc[nt][2] = -1e30f;
                    if (c0 + 1 > row1g) sc[nt][3] = -1e30f;
                }
            }
        }

        float rm0 = -1e30f, rm1 = -1e30f;
        #pragma unroll
        for (int nt = 0; nt < 8; nt++) {
            rm0 = fmaxf(rm0, fmaxf(sc[nt][0], sc[nt][1]));
            rm1 = fmaxf(rm1, fmaxf(sc[nt][2], sc[nt][3]));
        }
        rm0 = fmaxf(rm0, __shfl_xor_sync(0xffffffffu, rm0, 1));
        rm0 = fmaxf(rm0, __shfl_xor_sync(0xffffffffu, rm0, 2));
        rm1 = fmaxf(rm1, __shfl_xor_sync(0xffffffffu, rm1, 1));
        rm1 = fmaxf(rm1, __shfl_xor_sync(0xffffffffu, rm1, 2));

        float nm0 = fmaxf(m0, rm0), nm1 = fmaxf(m1, rm1);
        float a0 = __expf(m0 - nm0), a1 = __expf(m1 - nm1);
        m0 = nm0; m1 = nm1;

        float rs0 = 0.f, rs1 = 0.f;
        #pragma unroll
        for (int nt = 0; nt < 8; nt++) {
            float p0 = __expf(sc[nt][0] - nm0); sc[nt][0] = p0; rs0 += p0;
            float p1 = __expf(sc[nt][1] - nm0); sc[nt][1] = p1; rs0 += p1;
            float p2 = __expf(sc[nt][2] - nm1); sc[nt][2] = p2; rs1 += p2;
            float p3 = __expf(sc[nt][3] - nm1); sc[nt][3] = p3; rs1 += p3;
        }
        rs0 += __shfl_xor_sync(0xffffffffu, rs0, 1);
        rs0 += __shfl_xor_sync(0xffffffffu, rs0, 2);
        rs1 += __shfl_xor_sync(0xffffffffu, rs1, 1);
        rs1 += __shfl_xor_sync(0xffffffffu, rs1, 2);
        l0 = l0 * a0 + rs0;
        l1 = l1 * a1 + rs1;

        #pragma unroll
        for (int nt = 0; nt < 8; nt++) {
            o[nt][0] *= a0; o[nt][1] *= a0;
            o[nt][2] *= a1; o[nt][3] *= a1;
        }

        // P -> smem (A-layout, warp-private blocks), 2 STS.64 per nt
        #pragma unroll
        for (int nt = 0; nt < 8; nt++) {
            unsigned blkb = (unsigned)((nt * 8 + w) * 512);
            unsigned sw = ((unsigned)(nt & 3)) << 4;
            uint2 v0, v1;
            v0.x = f2tf(sc[nt][0]); v0.y = f2tf(sc[nt][2]);
            v1.x = f2tf(sc[nt][1]); v1.y = f2tf(sc[nt][3]);
            *(uint2*)(Pb + ((blkb + pbase) ^ sw)) = v0;
            *(uint2*)(Pb + ((blkb + pbase + 16) ^ sw)) = v1;
        }
        __syncwarp();

        // O += P V  (P a-frags via LDS.128; V b-frags via ldmatrix on V^T)
        #pragma unroll
        for (int kk8 = 0; kk8 < 8; kk8++) {
            const unsigned ax = ((unsigned)lane << 4) ^ ((unsigned)(kk8 & 3) << 4);
            uint4 a = *(const uint4*)(Pb + ((kk8 * 8 + w) << 9) + ax);
            #pragma unroll
            for (int i = 0; i < 4; i++) {
                uint4 bq = ldsm4(bwV + (unsigned)(i * 16) * QST2 + kk8 * 32);
                mma8(o[2 * i + 0], a, make_uint2(bq.x, bq.y));
                mma8(o[2 * i + 1], a, make_uint2(bq.z, bq.w));
            }
        }
        __syncthreads();
    }

    // epilogue: normalize, pre-round, write ctx
    float inv0 = 1.f / l0, inv1 = 1.f / l1;
    #pragma unroll
    for (int nt = 0; nt < 8; nt++) {
        int colg = h * HD + nt * 8 + tq * 2;
        size_t r0 = (size_t)(b * SEQ + row0g) * D_MODEL + colg;
        size_t r1 = (size_t)(b * SEQ + row1g) * D_MODEL + colg;
        g_ctx[r0]     = __uint_as_float(f2tf(o[nt][0] * inv0));
        g_ctx[r0 + 1] = __uint_as_float(f2tf(o[nt][1] * inv0));
        g_ctx[r1]     = __uint_as_float(f2tf(o[nt][2] * inv1));
        g_ctx[r1 + 1] = __uint_as_float(f2tf(o[nt][3] * inv1));
    }
}

// ============================================================================
extern "C" void kernel_launch(void* const* d_in, const int* in_sizes, int n_in,
                              void* d_out, int out_size)
{
    const float* x  = (const float*)d_in[0];
    const float* qW = (const float*)d_in[1];
    const float* kW = (const float*)d_in[2];
    const float* vW = (const float*)d_in[3];
    const float* oW = (const float*)d_in[4];
    float* out = (float*)d_out;

    float *pq, *pk, *pv, *pctx, *pxr, *pwr;
    cudaGetSymbolAddress((void**)&pq, g_q);
    cudaGetSymbolAddress((void**)&pk, g_k);
    cudaGetSymbolAddress((void**)&pv, g_v);
    cudaGetSymbolAddress((void**)&pctx, g_ctx);
    cudaGetSymbolAddress((void**)&pxr, g_xr);
    cudaGetSymbolAddress((void**)&pwr, g_wr);
    float* pw0 = pwr;
    float* pw1 = pwr + D_MODEL * D_MODEL;
    float* pw2 = pwr + 2 * D_MODEL * D_MODEL;
    float* pw3 = pwr + 3 * D_MODEL * D_MODEL;

    cudaFuncSetAttribute(gemm_tc, cudaFuncAttributeMaxDynamicSharedMemorySize, GSMEM);
    cudaFuncSetAttribute(flash_kernel, cudaFuncAttributeMaxDynamicSharedMemorySize, FSMEM);

    round_tf32<<<dim3(512, 5), 256>>>(
        (const float4*)x,  (float4*)pxr,
        (const float4*)qW, (float4*)pw0,
        (const float4*)kW, (float4*)pw1,
        (const float4*)vW, (float4*)pw2,
        (const float4*)oW, (float4*)pw3);

    dim3 ggridQKV(D_MODEL / TBN, MROWS / TBM, 3);
    gemm_tc<<<ggridQKV, 256, GSMEM>>>(pxr, pw0, pw1, pw2, pq, pk, pv, 1);

    flash_kernel<<<dim3(SEQ / QT, BATCH * NH), 256, FSMEM>>>();

    dim3 ggridO(D_MODEL / TBN, MROWS / TBM, 1);
    gemm_tc<<<ggridO, 256, GSMEM>>>(pctx, pw3, pw3, pw3, out, out, out, 0);
}

// round 13
// speedup vs baseline: 1.8148x; 1.0402x over previous
#include <cuda_runtime.h>
#include <cuda_bf16.h>
#include <math.h>

#define D_MODEL 1024
#define NH 16
#define HD 64
#define BATCH 2
#define SEQ 2048
#define MROWS (BATCH*SEQ)

// Scratch. q: pre-scaled(1/8)+tf32-rounded [B,H,S,HD]. k: rounded [B,H,S,HD].
// v: rounded TRANSPOSED [B,H,HD,S]. ctx: rounded [B*S, D_MODEL].
__device__ float g_q[BATCH*NH*SEQ*HD];
__device__ float g_k[BATCH*NH*SEQ*HD];
__device__ float g_v[BATCH*NH*SEQ*HD];
__device__ float g_ctx[MROWS*D_MODEL];
__device__ float g_xr[MROWS*D_MODEL];
__device__ float g_wr[4*D_MODEL*D_MODEL];

__device__ __forceinline__ unsigned f2tf(float x) {
    unsigned r;
    asm("cvt.rna.tf32.f32 %0, %1;" : "=r"(r) : "f"(x));
    return r;
}

__device__ __forceinline__ void mma8(float* c, uint4 a, uint2 b) {
    asm volatile(
        "mma.sync.aligned.m16n8k8.row.col.f32.tf32.tf32.f32 "
        "{%0,%1,%2,%3}, {%4,%5,%6,%7}, {%8,%9}, {%0,%1,%2,%3};"
        : "+f"(c[0]), "+f"(c[1]), "+f"(c[2]), "+f"(c[3])
        : "r"(a.x), "r"(a.y), "r"(a.z), "r"(a.w), "r"(b.x), "r"(b.y));
}

__device__ __forceinline__ uint4 ldsm4(unsigned a) {
    uint4 r;
    asm volatile("ldmatrix.sync.aligned.m8n8.x4.shared.b16 {%0,%1,%2,%3}, [%4];"
        : "=r"(r.x), "=r"(r.y), "=r"(r.z), "=r"(r.w) : "r"(a));
    return r;
}

__device__ __forceinline__ void cpa16(unsigned dst, const void* src) {
    asm volatile("cp.async.cg.shared.global [%0], [%1], 16;" :: "r"(dst), "l"(src));
}

// ============================================================================
// Prologue: round x and weights to tf32 bits
// ============================================================================
__global__ void round_tf32(const float4* s0, float4* d0,
                           const float4* s1, float4* d1,
                           const float4* s2, float4* d2,
                           const float4* s3, float4* d3,
                           const float4* s4, float4* d4)
{
    int z = blockIdx.y;
    const float4* s;
    float4* d;
    int n4;
    if (z == 0)      { s = s0; d = d0; n4 = MROWS * D_MODEL / 4; }
    else if (z == 1) { s = s1; d = d1; n4 = D_MODEL * D_MODEL / 4; }
    else if (z == 2) { s = s2; d = d2; n4 = D_MODEL * D_MODEL / 4; }
    else if (z == 3) { s = s3; d = d3; n4 = D_MODEL * D_MODEL / 4; }
    else             { s = s4; d = d4; n4 = D_MODEL * D_MODEL / 4; }
    for (int i = blockIdx.x * blockDim.x + threadIdx.x; i < n4;
         i += gridDim.x * blockDim.x) {
        float4 v = s[i];
        float4 r;
        r.x = __uint_as_float(f2tf(v.x));
        r.y = __uint_as_float(f2tf(v.y));
        r.z = __uint_as_float(f2tf(v.z));
        r.w = __uint_as_float(f2tf(v.w));
        d[i] = r;
    }
}

// ============================================================================
// TF32 GEMM (unchanged from R12): cp.async 3-stage -> ldmatrix.
// ============================================================================
#define TBM 128
#define TBN 128
#define TBK 32
#define RST 144
#define TILE_B (128*RST)
#define STAGE_B (2*TILE_B)
#define GSMEM (3*STAGE_B)       // 110592

__global__ __launch_bounds__(256, 2) void gemm_tc(
    const float* __restrict__ X,
    const float* __restrict__ W0, const float* __restrict__ W1, const float* __restrict__ W2,
    float* __restrict__ Y0, float* __restrict__ Y1, float* __restrict__ Y2,
    int proj_mode)
{
    extern __shared__ char gsm[];
    const unsigned sbase = (unsigned)__cvta_generic_to_shared(gsm);
    const int tid = threadIdx.x;
    const int wid = tid >> 5, lane = tid & 31;
    const int g = lane >> 2, tq = lane & 3;
    const int wm = wid & 1, wn = wid >> 1;
    const int bm = blockIdx.y * TBM, bn = blockIdx.x * TBN;
    const int z = blockIdx.z;
    const float* W = (z == 0) ? W0 : (z == 1) ? W1 : W2;
    float* Y = (z == 0) ? Y0 : (z == 1) ? Y1 : Y2;

    float acc[4][4][4];
    #pragma unroll
    for (int i = 0; i < 4; i++)
        #pragma unroll
        for (int j = 0; j < 4; j++)
            #pragma unroll
            for (int r = 0; r < 4; r++) acc[i][j][r] = 0.f;

    auto stage = [&](int j, int s) {
        const int kt = j * TBK;
        unsigned ab = sbase + (unsigned)s * STAGE_B;
        unsigned bb = ab + TILE_B;
        #pragma unroll
        for (int t = 0; t < 4; t++) {
            int c = t * 256 + tid, row = c >> 3, k16 = c & 7;
            cpa16(ab + row * RST + k16 * 16,
                  X + (size_t)(bm + row) * D_MODEL + kt + k16 * 4);
            cpa16(bb + row * RST + k16 * 16,
                  W + (size_t)(bn + row) * D_MODEL + kt + k16 * 4);
        }
        asm volatile("cp.async.commit_group;");
    };

    const unsigned laneOffA = (unsigned)(((lane & 7) + ((lane >> 3) & 1) * 8) * RST
                            + ((lane >> 4) & 1) * 16);
    const unsigned laneOffB = (unsigned)((((lane >> 4) & 1) * 8 + (lane & 7)) * RST
                            + ((lane >> 3) & 1) * 16);

    stage(0, 0);
    stage(1, 1);
    const int NCH = D_MODEL / TBK;
    for (int j = 0; j < NCH; j++) {
        if (j < NCH - 1) asm volatile("cp.async.wait_group 1;");
        else             asm volatile("cp.async.wait_group 0;");
        __syncthreads();
        if (j + 2 < NCH) stage(j + 2, (j + 2) % 3);

        unsigned ab = sbase + (unsigned)(j % 3) * STAGE_B;
        unsigned bb = ab + TILE_B;
        const unsigned awBase = ab + (unsigned)(wm * 64) * RST + laneOffA;
        const unsigned bwBase = bb + (unsigned)(wn * 32) * RST + laneOffB;
        #pragma unroll
        for (int kk8 = 0; kk8 < 4; kk8++) {
            uint4 a[4];
            #pragma unroll
            for (int mt = 0; mt < 4; mt++)
                a[mt] = ldsm4(awBase + (unsigned)(mt * 16) * RST + kk8 * 32);
            uint4 b0 = ldsm4(bwBase + kk8 * 32);
            uint4 b1 = ldsm4(bwBase + (unsigned)(16 * RST) + kk8 * 32);
            uint2 bf[4];
            bf[0] = make_uint2(b0.x, b0.y);
            bf[1] = make_uint2(b0.z, b0.w);
            bf[2] = make_uint2(b1.x, b1.y);
            bf[3] = make_uint2(b1.z, b1.w);
            #pragma unroll
            for (int mt = 0; mt < 4; mt++)
                #pragma unroll
                for (int nt = 0; nt < 4; nt++)
                    mma8(acc[mt][nt], a[mt], bf[nt]);
        }
        __syncthreads();
    }

    #pragma unroll
    for (int mt = 0; mt < 4; mt++) {
        #pragma unroll
        for (int nt = 0; nt < 4; nt++) {
            int row0 = bm + wm * 64 + mt * 16 + g;
            int col = bn + wn * 32 + nt * 8 + tq * 2;
            #pragma unroll
            for (int hh2 = 0; hh2 < 2; hh2++) {
                int row = row0 + hh2 * 8;
                float v0 = acc[mt][nt][hh2 * 2 + 0];
                float v1 = acc[mt][nt][hh2 * 2 + 1];
                if (proj_mode) {
                    int b2 = row >> 11, s2 = row & (SEQ - 1);
                    int hh = col >> 6, d0 = col & 63;
                    float r0, r1;
                    if (z == 0) {
                        r0 = __uint_as_float(f2tf(v0 * 0.125f));
                        r1 = __uint_as_float(f2tf(v1 * 0.125f));
                    } else {
                        r0 = __uint_as_float(f2tf(v0));
                        r1 = __uint_as_float(f2tf(v1));
                    }
                    if (z == 2) {
                        float* dst = Y + ((size_t)((b2 * NH + hh) * HD + d0)) * SEQ + s2;
                        dst[0] = r0; dst[SEQ] = r1;
                    } else {
                        float* dst = Y + ((size_t)((b2 * NH + hh) * SEQ + s2)) * HD + d0;
                        dst[0] = r0; dst[1] = r1;
                    }
                } else {
                    float* dst = Y + (size_t)row * D_MODEL + col;
                    dst[0] = v0; dst[1] = v1;
                }
            }
        }
    }
}

// ============================================================================
// Causal flash attention: cp.async DOUBLE-BUFFERED K/V + ldmatrix; P via
// in-warp shuffle transpose (no P smem). 128-row Q tiles, 8 warps, KT=64.
// ============================================================================
#define QT 128
#define KT 64
#define QST2 272
#define SQ_OFF 0                           // 128*272 = 34816
#define SK0_OFF 34816                      // 64*272 = 17408 each
#define SK1_OFF 52224
#define SV0_OFF 69632
#define SV1_OFF 87040
#define FSMEM 104448

__global__ __launch_bounds__(256, 2) void flash_kernel()
{
    extern __shared__ char smf[];
    const unsigned sbase = (unsigned)__cvta_generic_to_shared(smf);

    const int tid = threadIdx.x;
    const int w = tid >> 5, lane = tid & 31;
    const int g = lane >> 2, tq = lane & 3;
    const int bh = blockIdx.y;
    const int b = bh / NH, h = bh % NH;
    const int qt = (gridDim.x - 1 - blockIdx.x);
    const int q0 = qt * QT;

    const float* qbase = g_q + (size_t)(b * NH + h) * SEQ * HD + (size_t)q0 * HD;
    const float* kbase = g_k + (size_t)(b * NH + h) * SEQ * HD;
    const float* vtb   = g_v + (size_t)(b * NH + h) * SEQ * HD;   // [HD][SEQ]

    const int ktiles = 2 * qt + 2;

    // stage Q (group 0)
    #pragma unroll
    for (int i = 0; i < 8; i++) {
        int u = i * 256 + tid, row = u >> 4, k16 = u & 15;
        cpa16(sbase + SQ_OFF + row * QST2 + k16 * 16, qbase + row * HD + k16 * 4);
    }
    asm volatile("cp.async.commit_group;");

    auto stage_kv = [&](int ktile, int buf) {
        const int kv0 = ktile * KT;
        unsigned kb = sbase + (buf ? SK1_OFF : SK0_OFF);
        unsigned vb = sbase + (buf ? SV1_OFF : SV0_OFF);
        #pragma unroll
        for (int i = 0; i < 4; i++) {
            int u = i * 256 + tid, row = u >> 4, k16 = u & 15;
            cpa16(kb + row * QST2 + k16 * 16,
                  kbase + (size_t)(kv0 + row) * HD + k16 * 4);
            cpa16(vb + row * QST2 + k16 * 16,
                  vtb + (size_t)row * SEQ + kv0 + k16 * 4);
        }
        asm volatile("cp.async.commit_group;");
    };

    stage_kv(0, 0);
    stage_kv(1, 1);   // ktiles >= 2 always

    float o[8][4];
    #pragma unroll
    for (int nt = 0; nt < 8; nt++)
        #pragma unroll
        for (int r = 0; r < 4; r++) o[nt][r] = 0.f;
    float m0 = -INFINITY, m1 = -INFINITY, l0 = 0.f, l1 = 0.f;

    const int prow = w * 16 + g;
    const int row0g = q0 + prow;
    const int row1g = row0g + 8;

    const unsigned laneOffA = (unsigned)(((lane & 7) + ((lane >> 3) & 1) * 8) * QST2
                            + ((lane >> 4) & 1) * 16);
    const unsigned laneOffB = (unsigned)((((lane >> 4) & 1) * 8 + (lane & 7)) * QST2
                            + ((lane >> 3) & 1) * 16);
    const unsigned awQ = sbase + SQ_OFF + (unsigned)(w * 16) * QST2 + laneOffA;

    const int src1 = (lane & ~3) | (tq >> 1);
    const int src2 = src1 + 2;
    const bool odd = tq & 1;

    for (int kt = 0; kt < ktiles; kt++) {
        const int kv0 = kt * KT;
        const int buf = kt & 1;
        asm volatile("cp.async.wait_group 1;");
        __syncthreads();

        const unsigned bwK = sbase + (buf ? SK1_OFF : SK0_OFF) + laneOffB;
        const unsigned bwV = sbase + (buf ? SV1_OFF : SV0_OFF) + laneOffB;

        // S = Q K^T
        float sc[8][4];
        #pragma unroll
        for (int nt = 0; nt < 8; nt++)
            #pragma unroll
            for (int r = 0; r < 4; r++) sc[nt][r] = 0.f;
        #pragma unroll
        for (int kk8 = 0; kk8 < 8; kk8++) {
            uint4 a = ldsm4(awQ + kk8 * 32);
            #pragma unroll
            for (int i = 0; i < 4; i++) {
                uint4 bq = ldsm4(bwK + (unsigned)(i * 16) * QST2 + kk8 * 32);
                mma8(sc[2 * i + 0], a, make_uint2(bq.x, bq.y));
                mma8(sc[2 * i + 1], a, make_uint2(bq.z, bq.w));
            }
        }

        // causal mask
        const bool msk0 = (kv0 + KT - 1 > row0g);
        const bool msk1 = (kv0 + KT - 1 > row1g);
        if (msk0 | msk1) {
            #pragma unroll
            for (int nt = 0; nt < 8; nt++) {
                int c0 = kv0 + nt * 8 + tq * 2;
                if (msk0) {
                    if (c0     > row0g) sc[nt][0] = -1e30f;
                    if (c0 + 1 > row0g) sc[nt][1] = -1e30f;
                }
                if (msk1) {
                    if (c0     > row1g) sc[nt][2] = -1e30f;
                    if (c0 + 1 > row1g) sc[nt][3] = -1e30f;
                }
            }
        }

        // online softmax
        float rm0 = -1e30f, rm1 = -1e30f;
        #pragma unroll
        for (int nt = 0; nt < 8; nt++) {
            rm0 = fmaxf(rm0, fmaxf(sc[nt][0], sc[nt][1]));
            rm1 = fmaxf(rm1, fmaxf(sc[nt][2], sc[nt][3]));
        }
        rm0 = fmaxf(rm0, __shfl_xor_sync(0xffffffffu, rm0, 1));
        rm0 = fmaxf(rm0, __shfl_xor_sync(0xffffffffu, rm0, 2));
        rm1 = fmaxf(rm1, __shfl_xor_sync(0xffffffffu, rm1, 1));
        rm1 = fmaxf(rm1, __shfl_xor_sync(0xffffffffu, rm1, 2));

        float nm0 = fmaxf(m0, rm0), nm1 = fmaxf(m1, rm1);
        float a0 = __expf(m0 - nm0), a1 = __expf(m1 - nm1);
        m0 = nm0; m1 = nm1;

        float rs0 = 0.f, rs1 = 0.f;
        #pragma unroll
        for (int nt = 0; nt < 8; nt++) {
            float p0 = __expf(sc[nt][0] - nm0); sc[nt][0] = p0; rs0 += p0;
            float p1 = __expf(sc[nt][1] - nm0); sc[nt][1] = p1; rs0 += p1;
            float p2 = __expf(sc[nt][2] - nm1); sc[nt][2] = p2; rs1 += p2;
            float p3 = __expf(sc[nt][3] - nm1); sc[nt][3] = p3; rs1 += p3;
        }
        rs0 += __shfl_xor_sync(0xffffffffu, rs0, 1);
        rs0 += __shfl_xor_sync(0xffffffffu, rs0, 2);
        rs1 += __shfl_xor_sync(0xffffffffu, rs1, 1);
        rs1 += __shfl_xor_sync(0xffffffffu, rs1, 2);
        l0 = l0 * a0 + rs0;
        l1 = l1 * a1 + rs1;

        #pragma unroll
        for (int nt = 0; nt < 8; nt++) {
            o[nt][0] *= a0; o[nt][1] *= a0;
            o[nt][2] *= a1; o[nt][3] *= a1;
        }

        // O += P V: P a-frags via in-warp shuffle transpose of sc[kb]
        #pragma unroll
        for (int kb = 0; kb < 8; kb++) {
            float x0 = __shfl_sync(0xffffffffu, sc[kb][0], src1);
            float x1 = __shfl_sync(0xffffffffu, sc[kb][1], src1);
            float x2 = __shfl_sync(0xffffffffu, sc[kb][2], src1);
            float x3 = __shfl_sync(0xffffffffu, sc[kb][3], src1);
            float y0 = __shfl_sync(0xffffffffu, sc[kb][0], src2);
            float y1 = __shfl_sync(0xffffffffu, sc[kb][1], src2);
            float y2 = __shfl_sync(0xffffffffu, sc[kb][2], src2);
            float y3 = __shfl_sync(0xffffffffu, sc[kb][3], src2);
            uint4 a;
            a.x = f2tf(odd ? x1 : x0);
            a.y = f2tf(odd ? x3 : x2);
            a.z = f2tf(odd ? y1 : y0);
            a.w = f2tf(odd ? y3 : y2);
            #pragma unroll
            for (int i = 0; i < 4; i++) {
                uint4 bq = ldsm4(bwV + (unsigned)(i * 16) * QST2 + kb * 32);
                mma8(o[2 * i + 0], a, make_uint2(bq.x, bq.y));
                mma8(o[2 * i + 1], a, make_uint2(bq.z, bq.w));
            }
        }
        __syncthreads();                 // all warps done reading buf
        if (kt + 2 < ktiles) stage_kv(kt + 2, buf);
    }

    // epilogue: normalize, pre-round, write ctx
    float inv0 = 1.f / l0, inv1 = 1.f / l1;
    #pragma unroll
    for (int nt = 0; nt < 8; nt++) {
        int colg = h * HD + nt * 8 + tq * 2;
        size_t r0 = (size_t)(b * SEQ + row0g) * D_MODEL + colg;
        size_t r1 = (size_t)(b * SEQ + row1g) * D_MODEL + colg;
        g_ctx[r0]     = __uint_as_float(f2tf(o[nt][0] * inv0));
        g_ctx[r0 + 1] = __uint_as_float(f2tf(o[nt][1] * inv0));
        g_ctx[r1]     = __uint_as_float(f2tf(o[nt][2] * inv1));
        g_ctx[r1 + 1] = __uint_as_float(f2tf(o[nt][3] * inv1));
    }
}

// ============================================================================
extern "C" void kernel_launch(void* const* d_in, const int* in_sizes, int n_in,
                              void* d_out, int out_size)
{
    const float* x  = (const float*)d_in[0];
    const float* qW = (const float*)d_in[1];
    const float* kW = (const float*)d_in[2];
    const float* vW = (const float*)d_in[3];
    const float* oW = (const float*)d_in[4];
    float* out = (float*)d_out;

    float *pq, *pk, *pv, *pctx, *pxr, *pwr;
    cudaGetSymbolAddress((void**)&pq, g_q);
    cudaGetSymbolAddress((void**)&pk, g_k);
    cudaGetSymbolAddress((void**)&pv, g_v);
    cudaGetSymbolAddress((void**)&pctx, g_ctx);
    cudaGetSymbolAddress((void**)&pxr, g_xr);
    cudaGetSymbolAddress((void**)&pwr, g_wr);
    float* pw0 = pwr;
    float* pw1 = pwr + D_MODEL * D_MODEL;
    float* pw2 = pwr + 2 * D_MODEL * D_MODEL;
    float* pw3 = pwr + 3 * D_MODEL * D_MODEL;

    cudaFuncSetAttribute(gemm_tc, cudaFuncAttributeMaxDynamicSharedMemorySize, GSMEM);
    cudaFuncSetAttribute(flash_kernel, cudaFuncAttributeMaxDynamicSharedMemorySize, FSMEM);

    round_tf32<<<dim3(512, 5), 256>>>(
        (const float4*)x,  (float4*)pxr,
        (const float4*)qW, (float4*)pw0,
        (const float4*)kW, (float4*)pw1,
        (const float4*)vW, (float4*)pw2,
        (const float4*)oW, (float4*)pw3);

    dim3 ggridQKV(D_MODEL / TBN, MROWS / TBM, 3);
    gemm_tc<<<ggridQKV, 256, GSMEM>>>(pxr, pw0, pw1, pw2, pq, pk, pv, 1);

    flash_kernel<<<dim3(SEQ / QT, BATCH * NH), 256, FSMEM>>>();

    dim3 ggridO(D_MODEL / TBN, MROWS / TBM, 1);
    gemm_tc<<<ggridO, 256, GSMEM>>>(pctx, pw3, pw3, pw3, out, out, out, 0);
}